// round 2
// baseline (speedup 1.0000x reference)
#include <cuda_runtime.h>
#include <math_constants.h>

// Problem constants
#define BATCH   2
#define CH      256
#define FRAMES  16
#define NPIX    4096            // 64*64
#define BF      32              // BATCH*FRAMES
#define HEADS   8
#define DH      32
#define QKV_M   768             // 3*HEADS*DH
#define XSTRIDE (FRAMES*NPIX)   // stride between channels in x layout

// Scratch (no cudaMalloc allowed)
__device__ float g_qkv[(size_t)BF * QKV_M * NPIX];     // 402 MB
__device__ float g_ctx[(size_t)BF * HEADS * DH * DH];  // 1 MB
__device__ float g_wf [(size_t)BF * CH * CH];          // 8 MB

// ---------------------------------------------------------------------------
// Kernel 1: qkv[bi] = w_qkv (768x256) @ X[bi] (256x4096)
// X[bi][c][n] = x[((b*256+c)*16+f)*4096 + n]
// 128x128 block tile, K-tile 8, 256 threads, 8x8 per thread
// ---------------------------------------------------------------------------
__global__ void __launch_bounds__(256) k_qkv_gemm(const float* __restrict__ W,
                                                 const float* __restrict__ x,
                                                 float* __restrict__ qkv) {
    int bi = blockIdx.z;
    int b = bi >> 4, f = bi & 15;
    const float* X = x + ((size_t)b * CH * FRAMES + f) * NPIX;  // element (c,n): X[c*XSTRIDE + n]
    int m0 = blockIdx.y * 128;
    int n0 = blockIdx.x * 128;

    __shared__ float As[8][128];
    __shared__ float Bs[8][128];

    int tid = threadIdx.x;
    int tx = tid & 15, ty = tid >> 4;
    float acc[8][8] = {};

    for (int k0 = 0; k0 < CH; k0 += 8) {
        // A tile: 128 rows x 8 k, one float4 per thread
        {
            int m = tid >> 1;
            int kf = (tid & 1) * 4;
            float4 w4 = *(const float4*)&W[(size_t)(m0 + m) * CH + k0 + kf];
            As[kf + 0][m] = w4.x; As[kf + 1][m] = w4.y;
            As[kf + 2][m] = w4.z; As[kf + 3][m] = w4.w;
        }
        // B tile: 8 k x 128 n, one float4 per thread
        {
            int kk = tid >> 5;
            int nn = (tid & 31) * 4;
            float4 b4 = *(const float4*)&X[(size_t)(k0 + kk) * XSTRIDE + n0 + nn];
            Bs[kk][nn + 0] = b4.x; Bs[kk][nn + 1] = b4.y;
            Bs[kk][nn + 2] = b4.z; Bs[kk][nn + 3] = b4.w;
        }
        __syncthreads();
        #pragma unroll
        for (int kk = 0; kk < 8; kk++) {
            float a[8], bb[8];
            #pragma unroll
            for (int i = 0; i < 8; i++) a[i] = As[kk][ty * 8 + i];
            #pragma unroll
            for (int j = 0; j < 8; j++) bb[j] = Bs[kk][tx * 8 + j];
            #pragma unroll
            for (int i = 0; i < 8; i++)
                #pragma unroll
                for (int j = 0; j < 8; j++)
                    acc[i][j] += a[i] * bb[j];
        }
        __syncthreads();
    }

    float* out = qkv + (size_t)bi * QKV_M * NPIX;
    #pragma unroll
    for (int i = 0; i < 8; i++) {
        int m = m0 + ty * 8 + i;
        #pragma unroll
        for (int j = 0; j < 8; j += 4) {
            float4 v4 = make_float4(acc[i][j], acc[i][j+1], acc[i][j+2], acc[i][j+3]);
            *(float4*)&out[(size_t)m * NPIX + n0 + tx * 8 + j] = v4;
        }
    }
}

// ---------------------------------------------------------------------------
// Kernel 2: q softmax over d (32 strided rows) * scale, in place on q region
// ---------------------------------------------------------------------------
__global__ void k_q_softmax(float* __restrict__ qkv) {
    int n    = blockIdx.x * 256 + threadIdx.x;
    int head = blockIdx.y;
    int bi   = blockIdx.z;
    float* q = qkv + (size_t)bi * QKV_M * NPIX + (size_t)head * DH * NPIX + n;

    float vals[DH];
    float m = -CUDART_INF_F;
    #pragma unroll
    for (int d = 0; d < DH; d++) { vals[d] = q[(size_t)d * NPIX]; m = fmaxf(m, vals[d]); }
    float s = 0.f;
    #pragma unroll
    for (int d = 0; d < DH; d++) { vals[d] = __expf(vals[d] - m); s += vals[d]; }
    float inv = 0.17677669529663687f / s;   // scale = 32^-0.5
    #pragma unroll
    for (int d = 0; d < DH; d++) q[(size_t)d * NPIX] = vals[d] * inv;
}

// ---------------------------------------------------------------------------
// Kernel 3: k softmax over n fused with context[d][e] = sum_n k_sm[d,n]*v[e,n]
// One block (256 thr) per (bi, head)
// ---------------------------------------------------------------------------
__global__ void __launch_bounds__(256) k_context(const float* __restrict__ qkv,
                                                 float* __restrict__ ctx) {
    int head = blockIdx.x, bi = blockIdx.y;
    const float* kp = qkv + (size_t)bi * QKV_M * NPIX + (size_t)(CH + head * DH) * NPIX;
    const float* vp = qkv + (size_t)bi * QKV_M * NPIX + (size_t)(2 * CH + head * DH) * NPIX;

    __shared__ float m_s[DH], z_s[DH];
    int tid = threadIdx.x;
    int warp = tid >> 5, lane = tid & 31;

    // Phase 1: per-row max + sumexp (8 warps, 4 rows each)
    for (int r = warp; r < DH; r += 8) {
        const float* row = kp + (size_t)r * NPIX;
        float m = -CUDART_INF_F;
        for (int j = lane; j < NPIX; j += 32) m = fmaxf(m, row[j]);
        #pragma unroll
        for (int o = 16; o; o >>= 1) m = fmaxf(m, __shfl_xor_sync(0xffffffffu, m, o));
        float s = 0.f;
        for (int j = lane; j < NPIX; j += 32) s += __expf(row[j] - m);
        #pragma unroll
        for (int o = 16; o; o >>= 1) s += __shfl_xor_sync(0xffffffffu, s, o);
        if (lane == 0) { m_s[r] = m; z_s[r] = s; }
    }
    __syncthreads();

    // Phase 2: tiled rank-reduction over n
    __shared__ float kt[DH][129];
    __shared__ float vt[DH][129];
    int e = tid & 31, d8 = tid >> 5;         // thread covers (d8+8i, e)
    float acc[4] = {0.f, 0.f, 0.f, 0.f};

    for (int nn = 0; nn < NPIX; nn += 128) {
        __syncthreads();
        #pragma unroll
        for (int i = 0; i < 16; i++) {
            int idx = tid + i * 256;         // 0..4095
            int r = idx >> 7, j = idx & 127;
            kt[r][j] = __expf(kp[(size_t)r * NPIX + nn + j] - m_s[r]);
            vt[r][j] = vp[(size_t)r * NPIX + nn + j];
        }
        __syncthreads();
        #pragma unroll
        for (int j = 0; j < 128; j++) {
            float ve = vt[e][j];
            #pragma unroll
            for (int i = 0; i < 4; i++) acc[i] += kt[d8 + 8 * i][j] * ve;
        }
    }

    float* c = ctx + ((size_t)bi * HEADS + head) * (DH * DH);
    #pragma unroll
    for (int i = 0; i < 4; i++) {
        int d = d8 + 8 * i;
        c[d * DH + e] = acc[i] / z_s[d];
    }
}

// ---------------------------------------------------------------------------
// Kernel 4: fused weight Wf[bi][o][h*32+d] = sum_e w_out[o][h*32+e]*ctx[bi][h][d][e]
// One block per (head, bi)
// ---------------------------------------------------------------------------
__global__ void __launch_bounds__(256) k_wf(const float* __restrict__ w_out,
                                            const float* __restrict__ ctx,
                                            float* __restrict__ wf) {
    int head = blockIdx.x, bi = blockIdx.y;
    __shared__ float cs[DH][33];
    int tid = threadIdx.x;
    const float* c = ctx + ((size_t)bi * HEADS + head) * (DH * DH);
    for (int i = tid; i < DH * DH; i += 256) cs[i >> 5][i & 31] = c[i];
    __syncthreads();

    int d = tid & 31, og = tid >> 5;  // 8 o-groups
    for (int o = og; o < CH; o += 8) {
        const float* wrow = w_out + (size_t)o * CH + head * DH;
        float acc = 0.f;
        #pragma unroll
        for (int e = 0; e < DH; e++) acc += wrow[e] * cs[d][e];
        wf[(size_t)bi * CH * CH + (size_t)o * CH + head * DH + d] = acc;
    }
}

// ---------------------------------------------------------------------------
// Kernel 5: out[bi] = Wf[bi] (256x256) @ q_sm[bi] (256x4096) + b_out,
// scattered to (b, c, f, h, w) layout
// ---------------------------------------------------------------------------
__global__ void __launch_bounds__(256) k_out_gemm(const float* __restrict__ wf,
                                                  const float* __restrict__ qkv,
                                                  const float* __restrict__ bias,
                                                  float* __restrict__ out) {
    int bi = blockIdx.z;
    int b = bi >> 4, f = bi & 15;
    const float* A  = wf + (size_t)bi * CH * CH;          // 256x256, lda=256
    const float* Bq = qkv + (size_t)bi * QKV_M * NPIX;    // q rows 0..255, ldb=4096
    int m0 = blockIdx.y * 128;
    int n0 = blockIdx.x * 128;

    __shared__ float As[8][128];
    __shared__ float Bs[8][128];

    int tid = threadIdx.x;
    int tx = tid & 15, ty = tid >> 4;
    float acc[8][8] = {};

    for (int k0 = 0; k0 < CH; k0 += 8) {
        {
            int m = tid >> 1;
            int kf = (tid & 1) * 4;
            float4 w4 = *(const float4*)&A[(size_t)(m0 + m) * CH + k0 + kf];
            As[kf + 0][m] = w4.x; As[kf + 1][m] = w4.y;
            As[kf + 2][m] = w4.z; As[kf + 3][m] = w4.w;
        }
        {
            int kk = tid >> 5;
            int nn = (tid & 31) * 4;
            float4 b4 = *(const float4*)&Bq[(size_t)(k0 + kk) * NPIX + n0 + nn];
            Bs[kk][nn + 0] = b4.x; Bs[kk][nn + 1] = b4.y;
            Bs[kk][nn + 2] = b4.z; Bs[kk][nn + 3] = b4.w;
        }
        __syncthreads();
        #pragma unroll
        for (int kk = 0; kk < 8; kk++) {
            float a[8], bb[8];
            #pragma unroll
            for (int i = 0; i < 8; i++) a[i] = As[kk][ty * 8 + i];
            #pragma unroll
            for (int j = 0; j < 8; j++) bb[j] = Bs[kk][tx * 8 + j];
            #pragma unroll
            for (int i = 0; i < 8; i++)
                #pragma unroll
                for (int j = 0; j < 8; j++)
                    acc[i][j] += a[i] * bb[j];
        }
        __syncthreads();
    }

    #pragma unroll
    for (int i = 0; i < 8; i++) {
        int m = m0 + ty * 8 + i;
        float bo = bias[m];
        float* orow = out + ((size_t)(b * CH + m) * FRAMES + f) * NPIX;
        #pragma unroll
        for (int j = 0; j < 8; j += 4) {
            float4 v4 = make_float4(acc[i][j] + bo, acc[i][j+1] + bo,
                                    acc[i][j+2] + bo, acc[i][j+3] + bo);
            *(float4*)&orow[n0 + tx * 8 + j] = v4;
        }
    }
}

// ---------------------------------------------------------------------------
extern "C" void kernel_launch(void* const* d_in, const int* in_sizes, int n_in,
                              void* d_out, int out_size) {
    const float* x     = (const float*)d_in[0];
    const float* w_qkv = (const float*)d_in[1];
    const float* w_out = (const float*)d_in[2];
    const float* b_out = (const float*)d_in[3];
    float* out = (float*)d_out;

    float *qkv, *ctx, *wf;
    cudaGetSymbolAddress((void**)&qkv, g_qkv);
    cudaGetSymbolAddress((void**)&ctx, g_ctx);
    cudaGetSymbolAddress((void**)&wf,  g_wf);

    // 1. QKV projection
    k_qkv_gemm<<<dim3(NPIX / 128, QKV_M / 128, BF), 256>>>(w_qkv, x, qkv);
    // 2. q softmax over d (in place)
    k_q_softmax<<<dim3(NPIX / 256, HEADS, BF), 256>>>(qkv);
    // 3. k softmax + context
    k_context<<<dim3(HEADS, BF), 256>>>(qkv, ctx);
    // 4. fused weight
    k_wf<<<dim3(HEADS, BF), 256>>>(w_out, ctx, wf);
    // 5. output GEMM + bias + scatter
    k_out_gemm<<<dim3(NPIX / 128, CH / 128, BF), 256>>>(wf, qkv, b_out, out);
}

// round 4
// speedup vs baseline: 1.8021x; 1.8021x over previous
#include <cuda_runtime.h>
#include <cuda_bf16.h>
#include <math_constants.h>
#include <cstdint>

// Problem constants
#define BATCH   2
#define CH      256
#define FRAMES  16
#define NPIX    4096            // 64*64
#define BF      32              // BATCH*FRAMES
#define HEADS   8
#define DH      32
#define QKV_M   768             // 3*HEADS*DH
#define XSTRIDE (FRAMES*NPIX)   // stride between channels in x layout

// ---------------------------------------------------------------------------
// Scratch (__device__ globals; no cudaMalloc allowed)
// ---------------------------------------------------------------------------
__device__ float g_qkv[(size_t)BF * QKV_M * NPIX];          // fp32 qkv
__device__ float g_ctx[(size_t)BF * HEADS * DH * DH];
__device__ __nv_bfloat16 g_xhi[(size_t)BATCH * CH * FRAMES * NPIX];
__device__ __nv_bfloat16 g_xlo[(size_t)BATCH * CH * FRAMES * NPIX];
__device__ __nv_bfloat16 g_whi[(size_t)QKV_M * CH];
__device__ __nv_bfloat16 g_wlo[(size_t)QKV_M * CH];
__device__ __nv_bfloat16 g_qhi[(size_t)BF * CH * NPIX];
__device__ __nv_bfloat16 g_qlo[(size_t)BF * CH * NPIX];
__device__ __nv_bfloat16 g_wfhi[(size_t)BF * CH * CH];
__device__ __nv_bfloat16 g_wflo[(size_t)BF * CH * CH];

__device__ __forceinline__ uint32_t smem_u32(const void* p) {
    uint32_t a;
    asm("{ .reg .u64 t; cvta.to.shared.u64 t, %1; cvt.u32.u64 %0, t; }" : "=r"(a) : "l"(p));
    return a;
}

// ---------------------------------------------------------------------------
// Split fp32 -> bf16 hi/lo
// ---------------------------------------------------------------------------
__global__ void k_split(const float* __restrict__ src,
                        __nv_bfloat16* __restrict__ hi,
                        __nv_bfloat16* __restrict__ lo) {
    size_t i = ((size_t)blockIdx.x * 256 + threadIdx.x) * 4;
    float4 v = *(const float4*)(src + i);
    __nv_bfloat16 h0 = __float2bfloat16(v.x), h1 = __float2bfloat16(v.y);
    __nv_bfloat16 h2 = __float2bfloat16(v.z), h3 = __float2bfloat16(v.w);
    __nv_bfloat16 l0 = __float2bfloat16(v.x - __bfloat162float(h0));
    __nv_bfloat16 l1 = __float2bfloat16(v.y - __bfloat162float(h1));
    __nv_bfloat16 l2 = __float2bfloat16(v.z - __bfloat162float(h2));
    __nv_bfloat16 l3 = __float2bfloat16(v.w - __bfloat162float(h3));
    __nv_bfloat162* hp = (__nv_bfloat162*)(hi + i);
    __nv_bfloat162* lp = (__nv_bfloat162*)(lo + i);
    hp[0] = __nv_bfloat162(h0, h1); hp[1] = __nv_bfloat162(h2, h3);
    lp[0] = __nv_bfloat162(l0, l1); lp[1] = __nv_bfloat162(l2, l3);
}

// ---------------------------------------------------------------------------
// mma.sync bf16 GEMM with 3-product hi/lo split, fp32 accum.
// CTA tile 128x128, K-step 32, 4-stage cp.async pipeline, 8 warps (64x32 each)
// OUT_MODE=false: qkv[bi] = W(768x256) @ X(256x4096), fp32 -> g_qkv
// OUT_MODE=true : out[bi] = Wf(256x256) @ Qsm(256x4096) + bias, scatter
// ---------------------------------------------------------------------------
#define BM 128
#define BN 128
#define BK 32
#define STAGES 4
#define PA_B 80      // A row pitch bytes (40 bf16): 5 x 16B-banks -> conflict free
#define PB_B 272     // B row pitch bytes (136 bf16): 17 x 16B-banks -> conflict free
#define SZ_A (128 * PA_B)            // 10240
#define SZ_B (32 * PB_B)             // 8704
#define OFF_AH 0
#define OFF_AL SZ_A
#define OFF_BH (2 * SZ_A)
#define OFF_BL (2 * SZ_A + SZ_B)
#define STAGE_BYTES (2 * SZ_A + 2 * SZ_B)    // 37888
#define GEMM_SMEM (STAGES * STAGE_BYTES)     // 151552

__device__ __forceinline__ void cp16(uint32_t dst, const void* src) {
    asm volatile("cp.async.cg.shared.global [%0], [%1], 16;" :: "r"(dst), "l"(src) : "memory");
}
__device__ __forceinline__ void ldsm4(uint32_t* r, uint32_t addr) {
    asm volatile("ldmatrix.sync.aligned.m8n8.x4.shared.b16 {%0,%1,%2,%3}, [%4];"
                 : "=r"(r[0]), "=r"(r[1]), "=r"(r[2]), "=r"(r[3]) : "r"(addr));
}
__device__ __forceinline__ void ldsm4t(uint32_t* r, uint32_t addr) {
    asm volatile("ldmatrix.sync.aligned.m8n8.x4.trans.shared.b16 {%0,%1,%2,%3}, [%4];"
                 : "=r"(r[0]), "=r"(r[1]), "=r"(r[2]), "=r"(r[3]) : "r"(addr));
}
__device__ __forceinline__ void mma16816(float* c, const uint32_t* a, const uint32_t* b) {
    asm volatile("mma.sync.aligned.m16n8k16.row.col.f32.bf16.bf16.f32 "
                 "{%0,%1,%2,%3}, {%4,%5,%6,%7}, {%8,%9}, {%0,%1,%2,%3};"
                 : "+f"(c[0]), "+f"(c[1]), "+f"(c[2]), "+f"(c[3])
                 : "r"(a[0]), "r"(a[1]), "r"(a[2]), "r"(a[3]), "r"(b[0]), "r"(b[1]));
}

template <bool OUT_MODE>
__global__ void __launch_bounds__(256, 1) k_mma_gemm(const __nv_bfloat16* __restrict__ Ahi,
                                                     const __nv_bfloat16* __restrict__ Alo,
                                                     const __nv_bfloat16* __restrict__ Bhi,
                                                     const __nv_bfloat16* __restrict__ Blo,
                                                     const float* __restrict__ bias,
                                                     float* __restrict__ outp) {
    extern __shared__ char smem[];
    const uint32_t sb0 = smem_u32(smem);
    int tid = threadIdx.x, w = tid >> 5, lane = tid & 31;
    int bi = blockIdx.z, b = bi >> 4, f = bi & 15;
    int m0 = blockIdx.y * BM, n0 = blockIdx.x * BN;

    const __nv_bfloat16* aH = OUT_MODE ? Ahi + (size_t)bi * CH * CH : Ahi;
    const __nv_bfloat16* aL = OUT_MODE ? Alo + (size_t)bi * CH * CH : Alo;
    const size_t bstride = OUT_MODE ? (size_t)NPIX : (size_t)XSTRIDE;
    const __nv_bfloat16* bH = OUT_MODE ? Bhi + (size_t)bi * CH * NPIX + n0
                                       : Bhi + ((size_t)(b * CH) * FRAMES + f) * NPIX + n0;
    const __nv_bfloat16* bL = OUT_MODE ? Blo + (size_t)bi * CH * NPIX + n0
                                       : Blo + ((size_t)(b * CH) * FRAMES + f) * NPIX + n0;

    // --- per-thread load addressing (8 x cp.async of 16B per stage) ---
    int am0 = tid >> 1;                 // A chunk 0: m row
    int ac0 = (tid & 1) * 2;            // A chunk col (c in 0..3), chunks c, c+1... use pairs
    // A: 512 chunks (m = ch>>2, c = ch&3); thread t -> chunks t, t+256
    // B: 512 chunks (k = ch>>4, c = ch&15); thread t -> chunks t, t+256
    (void)am0; (void)ac0;

    auto load_stage = [&](int s, int kt) {
        uint32_t sb = sb0 + (uint32_t)s * STAGE_BYTES;
        int k0 = kt * BK;
        #pragma unroll
        for (int i = 0; i < 2; i++) {
            int ch = tid + i * 256;
            int m = ch >> 2, c = ch & 3;
            const __nv_bfloat16* gH = aH + (size_t)(m0 + m) * CH + k0 + c * 8;
            const __nv_bfloat16* gL = aL + (size_t)(m0 + m) * CH + k0 + c * 8;
            uint32_t d = sb + OFF_AH + m * PA_B + c * 16;
            cp16(d, gH);
            cp16(d + (OFF_AL - OFF_AH), gL);
        }
        #pragma unroll
        for (int i = 0; i < 2; i++) {
            int ch = tid + i * 256;
            int k = ch >> 4, c = ch & 15;
            const __nv_bfloat16* gH = bH + (size_t)(k0 + k) * bstride + c * 8;
            const __nv_bfloat16* gL = bL + (size_t)(k0 + k) * bstride + c * 8;
            uint32_t d = sb + OFF_BH + k * PB_B + c * 16;
            cp16(d, gH);
            cp16(d + (OFF_BL - OFF_BH), gL);
        }
        asm volatile("cp.async.commit_group;" ::: "memory");
    };

    // --- warp tiling ---
    int wm = (w & 1) * 64;              // warp m origin within CTA tile
    int wn = (w >> 1) * 32;             // warp n origin
    float acc[4][4][4];
    #pragma unroll
    for (int i = 0; i < 4; i++)
        #pragma unroll
        for (int j = 0; j < 4; j++)
            #pragma unroll
            for (int r = 0; r < 4; r++) acc[i][j][r] = 0.f;

    // ldmatrix lane address bases (within stage)
    uint32_t aAddr = OFF_AH + (uint32_t)(wm + (lane & 15)) * PA_B + (uint32_t)(lane >> 4) * 16;
    uint32_t bAddr = OFF_BH + (uint32_t)(lane & 15) * PB_B + (uint32_t)(lane >> 4) * 16
                   + (uint32_t)wn * 2;

    // prologue: stages 0..2
    #pragma unroll
    for (int s = 0; s < STAGES - 1; s++) load_stage(s, s);

    const int KT = CH / BK;   // 8
    for (int t = 0; t < KT; t++) {
        asm volatile("cp.async.wait_group %0;" :: "n"(STAGES - 2) : "memory");
        __syncthreads();
        if (t + STAGES - 1 < KT) load_stage((t + STAGES - 1) & (STAGES - 1), t + STAGES - 1);
        else asm volatile("cp.async.commit_group;" ::: "memory");

        uint32_t sb = sb0 + (uint32_t)(t & (STAGES - 1)) * STAGE_BYTES;
        #pragma unroll
        for (int ks = 0; ks < 2; ks++) {
            uint32_t aHf[4][4], aLf[4][4], bHf[2][4], bLf[2][4];
            #pragma unroll
            for (int mi = 0; mi < 4; mi++) {
                uint32_t ad = sb + aAddr + (uint32_t)(mi * 16) * PA_B + ks * 32;
                ldsm4(aHf[mi], ad);
                ldsm4(aLf[mi], ad + (OFF_AL - OFF_AH));
            }
            #pragma unroll
            for (int ng = 0; ng < 2; ng++) {
                uint32_t bd = sb + bAddr + (uint32_t)(ks * 16) * PB_B + ng * 32;
                ldsm4t(bHf[ng], bd);
                ldsm4t(bLf[ng], bd + (OFF_BL - OFF_BH));
            }
            #pragma unroll
            for (int mi = 0; mi < 4; mi++)
                #pragma unroll
                for (int ni = 0; ni < 4; ni++) {
                    const uint32_t* bh = &bHf[ni >> 1][(ni & 1) * 2];
                    const uint32_t* bl = &bLf[ni >> 1][(ni & 1) * 2];
                    mma16816(acc[mi][ni], aHf[mi], bh);
                    mma16816(acc[mi][ni], aHf[mi], bl);
                    mma16816(acc[mi][ni], aLf[mi], bh);
                }
        }
        __syncthreads();
    }

    // --- epilogue: fp32 direct stores ---
    #pragma unroll
    for (int mi = 0; mi < 4; mi++) {
        #pragma unroll
        for (int ni = 0; ni < 4; ni++) {
            int r0 = m0 + wm + mi * 16 + (lane >> 2);
            int r1 = r0 + 8;
            int cc = n0 + wn + ni * 8 + (lane & 3) * 2;
            if (OUT_MODE) {
                float b0 = bias[r0], b1 = bias[r1];
                float* p0 = outp + ((size_t)(b * CH + r0) * FRAMES + f) * NPIX + cc;
                float* p1 = outp + ((size_t)(b * CH + r1) * FRAMES + f) * NPIX + cc;
                *(float2*)p0 = make_float2(acc[mi][ni][0] + b0, acc[mi][ni][1] + b0);
                *(float2*)p1 = make_float2(acc[mi][ni][2] + b1, acc[mi][ni][3] + b1);
            } else {
                float* p0 = outp + (size_t)bi * QKV_M * NPIX + (size_t)r0 * NPIX + cc;
                float* p1 = outp + (size_t)bi * QKV_M * NPIX + (size_t)r1 * NPIX + cc;
                *(float2*)p0 = make_float2(acc[mi][ni][0], acc[mi][ni][1]);
                *(float2*)p1 = make_float2(acc[mi][ni][2], acc[mi][ni][3]);
            }
        }
    }
}

// ---------------------------------------------------------------------------
// q softmax over d (32 strided rows) * scale -> bf16 hi/lo
// ---------------------------------------------------------------------------
__global__ void k_q_softmax(const float* __restrict__ qkv,
                            __nv_bfloat16* __restrict__ qhi,
                            __nv_bfloat16* __restrict__ qlo) {
    int n    = blockIdx.x * 256 + threadIdx.x;
    int head = blockIdx.y;
    int bi   = blockIdx.z;
    const float* q = qkv + (size_t)bi * QKV_M * NPIX + (size_t)head * DH * NPIX + n;

    float vals[DH];
    float m = -CUDART_INF_F;
    #pragma unroll
    for (int d = 0; d < DH; d++) { vals[d] = q[(size_t)d * NPIX]; m = fmaxf(m, vals[d]); }
    float s = 0.f;
    #pragma unroll
    for (int d = 0; d < DH; d++) { vals[d] = __expf(vals[d] - m); s += vals[d]; }
    float inv = 0.17677669529663687f / s;   // scale = 32^-0.5
    size_t base = (size_t)bi * CH * NPIX + (size_t)(head * DH) * NPIX + n;
    #pragma unroll
    for (int d = 0; d < DH; d++) {
        float v = vals[d] * inv;
        __nv_bfloat16 h = __float2bfloat16(v);
        qhi[base + (size_t)d * NPIX] = h;
        qlo[base + (size_t)d * NPIX] = __float2bfloat16(v - __bfloat162float(h));
    }
}

// ---------------------------------------------------------------------------
// k softmax over n fused with context[d][e] = sum_n k_sm[d,n]*v[e,n]  (fp32)
// ---------------------------------------------------------------------------
__global__ void __launch_bounds__(256) k_context(const float* __restrict__ qkv,
                                                 float* __restrict__ ctx) {
    int head = blockIdx.x, bi = blockIdx.y;
    const float* kp = qkv + (size_t)bi * QKV_M * NPIX + (size_t)(CH + head * DH) * NPIX;
    const float* vp = qkv + (size_t)bi * QKV_M * NPIX + (size_t)(2 * CH + head * DH) * NPIX;

    __shared__ float m_s[DH], z_s[DH];
    int tid = threadIdx.x;
    int warp = tid >> 5, lane = tid & 31;

    for (int r = warp; r < DH; r += 8) {
        const float* row = kp + (size_t)r * NPIX;
        float m = -CUDART_INF_F;
        for (int j = lane; j < NPIX; j += 32) m = fmaxf(m, row[j]);
        #pragma unroll
        for (int o = 16; o; o >>= 1) m = fmaxf(m, __shfl_xor_sync(0xffffffffu, m, o));
        float s = 0.f;
        for (int j = lane; j < NPIX; j += 32) s += __expf(row[j] - m);
        #pragma unroll
        for (int o = 16; o; o >>= 1) s += __shfl_xor_sync(0xffffffffu, s, o);
        if (lane == 0) { m_s[r] = m; z_s[r] = s; }
    }
    __syncthreads();

    __shared__ float kt[DH][129];
    __shared__ float vt[DH][129];
    int e = tid & 31, d8 = tid >> 5;
    float acc[4] = {0.f, 0.f, 0.f, 0.f};

    for (int nn = 0; nn < NPIX; nn += 128) {
        __syncthreads();
        #pragma unroll
        for (int i = 0; i < 16; i++) {
            int idx = tid + i * 256;
            int r = idx >> 7, j = idx & 127;
            kt[r][j] = __expf(kp[(size_t)r * NPIX + nn + j] - m_s[r]);
            vt[r][j] = vp[(size_t)r * NPIX + nn + j];
        }
        __syncthreads();
        #pragma unroll
        for (int j = 0; j < 128; j++) {
            float ve = vt[e][j];
            #pragma unroll
            for (int i = 0; i < 4; i++) acc[i] += kt[d8 + 8 * i][j] * ve;
        }
    }

    float* c = ctx + ((size_t)bi * HEADS + head) * (DH * DH);
    #pragma unroll
    for (int i = 0; i < 4; i++) {
        int d = d8 + 8 * i;
        c[d * DH + e] = acc[i] / z_s[d];
    }
}

// ---------------------------------------------------------------------------
// fused weight Wf[bi][o][h*32+d] = sum_e w_out[o][h*32+e]*ctx[bi][h][d][e]
// -> bf16 hi/lo
// ---------------------------------------------------------------------------
__global__ void __launch_bounds__(256) k_wf(const float* __restrict__ w_out,
                                            const float* __restrict__ ctx,
                                            __nv_bfloat16* __restrict__ wfhi,
                                            __nv_bfloat16* __restrict__ wflo) {
    int head = blockIdx.x, bi = blockIdx.y;
    __shared__ float cs[DH][33];
    int tid = threadIdx.x;
    const float* c = ctx + ((size_t)bi * HEADS + head) * (DH * DH);
    for (int i = tid; i < DH * DH; i += 256) cs[i >> 5][i & 31] = c[i];
    __syncthreads();

    int d = tid & 31, og = tid >> 5;
    for (int o = og; o < CH; o += 8) {
        const float* wrow = w_out + (size_t)o * CH + head * DH;
        float acc = 0.f;
        #pragma unroll
        for (int e = 0; e < DH; e++) acc += wrow[e] * cs[d][e];
        size_t oidx = (size_t)bi * CH * CH + (size_t)o * CH + head * DH + d;
        __nv_bfloat16 h = __float2bfloat16(acc);
        wfhi[oidx] = h;
        wflo[oidx] = __float2bfloat16(acc - __bfloat162float(h));
    }
}

// ---------------------------------------------------------------------------
extern "C" void kernel_launch(void* const* d_in, const int* in_sizes, int n_in,
                              void* d_out, int out_size) {
    const float* x     = (const float*)d_in[0];
    const float* w_qkv = (const float*)d_in[1];
    const float* w_out = (const float*)d_in[2];
    const float* b_out = (const float*)d_in[3];
    float* out = (float*)d_out;

    float *qkv, *ctx;
    __nv_bfloat16 *xhi, *xlo, *whi, *wlo, *qhi, *qlo, *wfhi, *wflo;
    cudaGetSymbolAddress((void**)&qkv,  g_qkv);
    cudaGetSymbolAddress((void**)&ctx,  g_ctx);
    cudaGetSymbolAddress((void**)&xhi,  g_xhi);
    cudaGetSymbolAddress((void**)&xlo,  g_xlo);
    cudaGetSymbolAddress((void**)&whi,  g_whi);
    cudaGetSymbolAddress((void**)&wlo,  g_wlo);
    cudaGetSymbolAddress((void**)&qhi,  g_qhi);
    cudaGetSymbolAddress((void**)&qlo,  g_qlo);
    cudaGetSymbolAddress((void**)&wfhi, g_wfhi);
    cudaGetSymbolAddress((void**)&wflo, g_wflo);

    cudaFuncSetAttribute(k_mma_gemm<false>, cudaFuncAttributeMaxDynamicSharedMemorySize, GEMM_SMEM);
    cudaFuncSetAttribute(k_mma_gemm<true>,  cudaFuncAttributeMaxDynamicSharedMemorySize, GEMM_SMEM);

    // 0. split inputs to bf16 hi/lo
    k_split<<<(BATCH * CH * FRAMES * NPIX) / 1024, 256>>>(x, xhi, xlo);
    k_split<<<(QKV_M * CH) / 1024, 256>>>(w_qkv, whi, wlo);
    // 1. QKV projection (mma.sync tensor cores) -> fp32 qkv
    k_mma_gemm<false><<<dim3(NPIX / BN, QKV_M / BM, BF), 256, GEMM_SMEM>>>(
        whi, wlo, xhi, xlo, nullptr, qkv);
    // 2. q softmax over d -> bf16 hi/lo
    k_q_softmax<<<dim3(NPIX / 256, HEADS, BF), 256>>>(qkv, qhi, qlo);
    // 3. k softmax + context (fp32)
    k_context<<<dim3(HEADS, BF), 256>>>(qkv, ctx);
    // 4. fused weight -> bf16 hi/lo
    k_wf<<<dim3(HEADS, BF), 256>>>(w_out, ctx, wfhi, wflo);
    // 5. output GEMM (mma.sync) + bias + scatter
    k_mma_gemm<true><<<dim3(NPIX / BN, CH / BM, BF), 256, GEMM_SMEM>>>(
        wfhi, wflo, qhi, qlo, b_out, out);
}

// round 6
// speedup vs baseline: 2.0946x; 1.1623x over previous
#include <cuda_runtime.h>
#include <cuda_bf16.h>
#include <cuda_fp16.h>
#include <math_constants.h>
#include <cstdint>

// Problem constants
#define BATCH   2
#define CH      256
#define FRAMES  16
#define NPIX    4096
#define BF      32
#define HEADS   8
#define DH      32
#define QKV_M   768
#define XSTRIDE (FRAMES*NPIX)

// ---------------------------------------------------------------------------
// Scratch
// ---------------------------------------------------------------------------
__device__ float g_qkv[(size_t)BF * QKV_M * NPIX];
__device__ float g_ctx[(size_t)BF * HEADS * DH * DH];
__device__ __half g_xh[(size_t)BATCH * CH * FRAMES * NPIX];   // x as single fp16
__device__ __half g_wh[(size_t)QKV_M * CH];                   // W fp16 hi
__device__ __half g_wl[(size_t)QKV_M * CH];                   // W fp16 lo
__device__ __nv_bfloat16 g_qhi[(size_t)BF * CH * NPIX];
__device__ __nv_bfloat16 g_qlo[(size_t)BF * CH * NPIX];
__device__ __nv_bfloat16 g_wfhi[(size_t)BF * CH * CH];
__device__ __nv_bfloat16 g_wflo[(size_t)BF * CH * CH];

__device__ __forceinline__ uint32_t smem_u32(const void* p) {
    uint32_t a;
    asm("{ .reg .u64 t; cvta.to.shared.u64 t, %1; cvt.u32.u64 %0, t; }" : "=r"(a) : "l"(p));
    return a;
}
__device__ __forceinline__ void cp16(uint32_t dst, const void* src) {
    asm volatile("cp.async.cg.shared.global [%0], [%1], 16;" :: "r"(dst), "l"(src) : "memory");
}
__device__ __forceinline__ void ldsm4(uint32_t* r, uint32_t addr) {
    asm volatile("ldmatrix.sync.aligned.m8n8.x4.shared.b16 {%0,%1,%2,%3}, [%4];"
                 : "=r"(r[0]), "=r"(r[1]), "=r"(r[2]), "=r"(r[3]) : "r"(addr));
}
__device__ __forceinline__ void ldsm4t(uint32_t* r, uint32_t addr) {
    asm volatile("ldmatrix.sync.aligned.m8n8.x4.trans.shared.b16 {%0,%1,%2,%3}, [%4];"
                 : "=r"(r[0]), "=r"(r[1]), "=r"(r[2]), "=r"(r[3]) : "r"(addr));
}
__device__ __forceinline__ void mma_bf16(float* c, const uint32_t* a, const uint32_t* b) {
    asm volatile("mma.sync.aligned.m16n8k16.row.col.f32.bf16.bf16.f32 "
                 "{%0,%1,%2,%3}, {%4,%5,%6,%7}, {%8,%9}, {%0,%1,%2,%3};"
                 : "+f"(c[0]), "+f"(c[1]), "+f"(c[2]), "+f"(c[3])
                 : "r"(a[0]), "r"(a[1]), "r"(a[2]), "r"(a[3]), "r"(b[0]), "r"(b[1]));
}
__device__ __forceinline__ void mma_fp16(float* c, const uint32_t* a, const uint32_t* b) {
    asm volatile("mma.sync.aligned.m16n8k16.row.col.f32.f16.f16.f32 "
                 "{%0,%1,%2,%3}, {%4,%5,%6,%7}, {%8,%9}, {%0,%1,%2,%3};"
                 : "+f"(c[0]), "+f"(c[1]), "+f"(c[2]), "+f"(c[3])
                 : "r"(a[0]), "r"(a[1]), "r"(a[2]), "r"(a[3]), "r"(b[0]), "r"(b[1]));
}

// ---------------------------------------------------------------------------
// Splits
// ---------------------------------------------------------------------------
__global__ void k_split_w(const float* __restrict__ src,
                          __half* __restrict__ hi, __half* __restrict__ lo) {
    size_t i = ((size_t)blockIdx.x * 256 + threadIdx.x) * 4;
    float4 v = *(const float4*)(src + i);
    __half h0 = __float2half(v.x), h1 = __float2half(v.y);
    __half h2 = __float2half(v.z), h3 = __float2half(v.w);
    __half l0 = __float2half(v.x - __half2float(h0));
    __half l1 = __float2half(v.y - __half2float(h1));
    __half l2 = __float2half(v.z - __half2float(h2));
    __half l3 = __float2half(v.w - __half2float(h3));
    __half2* hp = (__half2*)(hi + i);
    __half2* lp = (__half2*)(lo + i);
    hp[0] = __half2(h0, h1); hp[1] = __half2(h2, h3);
    lp[0] = __half2(l0, l1); lp[1] = __half2(l2, l3);
}
__global__ void k_split_x(const float* __restrict__ src, __half* __restrict__ dst) {
    size_t i = ((size_t)blockIdx.x * 256 + threadIdx.x) * 4;
    float4 v = *(const float4*)(src + i);
    __half2* dp = (__half2*)(dst + i);
    dp[0] = __half2(__float2half(v.x), __float2half(v.y));
    dp[1] = __half2(__float2half(v.z), __float2half(v.w));
}

// ---------------------------------------------------------------------------
// Persistent-A GEMM.
// A tile (128 x 256, hi+lo) resident in smem for the whole CTA; B streamed
// per (n-tile, k-tile) with a 2-stage cp.async pipeline.
// OUT_MODE=false: 2-product fp16: qkv = (Wh+Wl)(768x256) @ xh(256x4096)
// OUT_MODE=true : 3-product bf16: out = Wf(256x256) @ Qsm(256x4096) + bias
// ---------------------------------------------------------------------------
#define PA     528                        // A row pitch bytes (512 data + 16) -> 33 banks, odd
#define SZ_A   (128 * PA)                 // 67584 per half
#define PB     272                        // B row pitch
#define SZ_B   (32 * PB)                  // 8704 per half-stage
#define OFF_B  (2 * SZ_A)                 // 135168

template <bool OUT_MODE>
__global__ void __launch_bounds__(256, 1) k_pgemm(const void* __restrict__ Ah_g,
                                                  const void* __restrict__ Al_g,
                                                  const void* __restrict__ Bh_g,
                                                  const void* __restrict__ Bl_g,
                                                  const float* __restrict__ bias,
                                                  float* __restrict__ outp) {
    constexpr int B_STAGE = OUT_MODE ? 2 * SZ_B : SZ_B;
    constexpr int NITER   = OUT_MODE ? 8 : 16;
    extern __shared__ char smem[];
    const uint32_t sb0 = smem_u32(smem);

    int tid = threadIdx.x, w = tid >> 5, lane = tid & 31;
    int m0 = blockIdx.y * 128;
    int bi = blockIdx.z, b = bi >> 4, f = bi & 15;
    int n_start = blockIdx.x * NITER * 128;

    const char* Ah = (const char*)Ah_g + (OUT_MODE ? (size_t)bi * CH * CH * 2 : 0);
    const char* Al = (const char*)Al_g + (OUT_MODE ? (size_t)bi * CH * CH * 2 : 0);
    const size_t bstride = OUT_MODE ? (size_t)NPIX : (size_t)XSTRIDE;
    const size_t bbase   = OUT_MODE ? (size_t)bi * CH * NPIX
                                    : ((size_t)(b * CH) * FRAMES + f) * NPIX;
    const char* Bh = (const char*)Bh_g + bbase * 2;
    const char* Bl = OUT_MODE ? (const char*)Bl_g + bbase * 2 : nullptr;

    // ---- load A (full K) once: group 0 ----
    #pragma unroll
    for (int i = 0; i < 16; i++) {
        int ch = tid + i * 256;
        int r = ch >> 5, c = ch & 31;
        size_t goff = ((size_t)(m0 + r) * CH + c * 8) * 2;
        uint32_t d = sb0 + r * PA + c * 16;
        cp16(d, Ah + goff);
        cp16(d + SZ_A, Al + goff);
    }
    asm volatile("cp.async.commit_group;" ::: "memory");

    auto loadB = [&](int c) {
        int nt = c >> 3, kt = c & 7;
        int nb = n_start + nt * 128;
        uint32_t sb = sb0 + OFF_B + (uint32_t)(c & 1) * B_STAGE;
        #pragma unroll
        for (int i = 0; i < 2; i++) {
            int ch = tid + i * 256;
            int r = ch >> 4, cc = ch & 15;
            size_t goff = ((size_t)(kt * 32 + r) * bstride + nb + cc * 8) * 2;
            uint32_t d = sb + r * PB + cc * 16;
            cp16(d, Bh + goff);
            if (OUT_MODE) cp16(d + SZ_B, Bl + goff);
        }
        asm volatile("cp.async.commit_group;" ::: "memory");
    };

    int wm = (w & 1) * 64;
    int wn = (w >> 1) * 32;
    uint32_t aAddr = sb0 + (uint32_t)(wm + (lane & 15)) * PA + (uint32_t)(lane >> 4) * 16;
    uint32_t bAddr = (uint32_t)(lane & 15) * PB + (uint32_t)(lane >> 4) * 16
                   + (uint32_t)wn * 2;

    loadB(0);
    const int C = NITER * 8;

    for (int nt = 0; nt < NITER; nt++) {
        float acc[4][4][4];
        #pragma unroll
        for (int i = 0; i < 4; i++)
            #pragma unroll
            for (int j = 0; j < 4; j++)
                #pragma unroll
                for (int r = 0; r < 4; r++) acc[i][j][r] = 0.f;

        for (int kt = 0; kt < 8; kt++) {
            int c = nt * 8 + kt;
            if (c + 1 < C) loadB(c + 1);
            else asm volatile("cp.async.commit_group;" ::: "memory");
            asm volatile("cp.async.wait_group %0;" :: "n"(1) : "memory");
            __syncthreads();

            uint32_t sb = sb0 + OFF_B + (uint32_t)(c & 1) * B_STAGE;
            #pragma unroll
            for (int ks = 0; ks < 2; ks++) {
                uint32_t aHf[4][4], aLf[4][4], bHf[2][4], bLf[2][4];
                #pragma unroll
                for (int mi = 0; mi < 4; mi++) {
                    uint32_t ad = aAddr + (uint32_t)(mi * 16) * PA + kt * 64 + ks * 32;
                    ldsm4(aHf[mi], ad);
                    ldsm4(aLf[mi], ad + SZ_A);
                }
                #pragma unroll
                for (int ng = 0; ng < 2; ng++) {
                    uint32_t bd = sb + bAddr + (uint32_t)(ks * 16) * PB + ng * 32;
                    ldsm4t(bHf[ng], bd);
                    if (OUT_MODE) ldsm4t(bLf[ng], bd + SZ_B);
                }
                #pragma unroll
                for (int mi = 0; mi < 4; mi++)
                    #pragma unroll
                    for (int ni = 0; ni < 4; ni++) {
                        const uint32_t* bh = &bHf[ni >> 1][(ni & 1) * 2];
                        if (OUT_MODE) {
                            const uint32_t* bl = &bLf[ni >> 1][(ni & 1) * 2];
                            mma_bf16(acc[mi][ni], aHf[mi], bh);
                            mma_bf16(acc[mi][ni], aHf[mi], bl);
                            mma_bf16(acc[mi][ni], aLf[mi], bh);
                        } else {
                            mma_fp16(acc[mi][ni], aHf[mi], bh);
                            mma_fp16(acc[mi][ni], aLf[mi], bh);
                        }
                    }
            }
            __syncthreads();
        }

        // epilogue for this n-tile
        int n0 = n_start + nt * 128;
        #pragma unroll
        for (int mi = 0; mi < 4; mi++) {
            #pragma unroll
            for (int ni = 0; ni < 4; ni++) {
                int r0 = m0 + wm + mi * 16 + (lane >> 2);
                int r1 = r0 + 8;
                int cc = n0 + wn + ni * 8 + (lane & 3) * 2;
                if (OUT_MODE) {
                    float b0 = bias[r0], b1 = bias[r1];
                    float* p0 = outp + ((size_t)(b * CH + r0) * FRAMES + f) * NPIX + cc;
                    float* p1 = outp + ((size_t)(b * CH + r1) * FRAMES + f) * NPIX + cc;
                    *(float2*)p0 = make_float2(acc[mi][ni][0] + b0, acc[mi][ni][1] + b0);
                    *(float2*)p1 = make_float2(acc[mi][ni][2] + b1, acc[mi][ni][3] + b1);
                } else {
                    float* p0 = outp + (size_t)bi * QKV_M * NPIX + (size_t)r0 * NPIX + cc;
                    float* p1 = outp + (size_t)bi * QKV_M * NPIX + (size_t)r1 * NPIX + cc;
                    *(float2*)p0 = make_float2(acc[mi][ni][0], acc[mi][ni][1]);
                    *(float2*)p1 = make_float2(acc[mi][ni][2], acc[mi][ni][3]);
                }
            }
        }
    }
}

#define SMEM_QKV (OFF_B + 2 * SZ_B)        // 152576
#define SMEM_OUT (OFF_B + 4 * SZ_B)        // 169984

// ---------------------------------------------------------------------------
// q softmax over d -> bf16 hi/lo
// ---------------------------------------------------------------------------
__global__ void k_q_softmax(const float* __restrict__ qkv,
                            __nv_bfloat16* __restrict__ qhi,
                            __nv_bfloat16* __restrict__ qlo) {
    int n    = blockIdx.x * 256 + threadIdx.x;
    int head = blockIdx.y;
    int bi   = blockIdx.z;
    const float* q = qkv + (size_t)bi * QKV_M * NPIX + (size_t)head * DH * NPIX + n;

    float vals[DH];
    float m = -CUDART_INF_F;
    #pragma unroll
    for (int d = 0; d < DH; d++) { vals[d] = q[(size_t)d * NPIX]; m = fmaxf(m, vals[d]); }
    float s = 0.f;
    #pragma unroll
    for (int d = 0; d < DH; d++) { vals[d] = __expf(vals[d] - m); s += vals[d]; }
    float inv = 0.17677669529663687f / s;
    size_t base = (size_t)bi * CH * NPIX + (size_t)(head * DH) * NPIX + n;
    #pragma unroll
    for (int d = 0; d < DH; d++) {
        float v = vals[d] * inv;
        __nv_bfloat16 h = __float2bfloat16(v);
        qhi[base + (size_t)d * NPIX] = h;
        qlo[base + (size_t)d * NPIX] = __float2bfloat16(v - __bfloat162float(h));
    }
}

// ---------------------------------------------------------------------------
// k softmax over n fused with context
// ---------------------------------------------------------------------------
__global__ void __launch_bounds__(256) k_context(const float* __restrict__ qkv,
                                                 float* __restrict__ ctx) {
    int head = blockIdx.x, bi = blockIdx.y;
    const float* kp = qkv + (size_t)bi * QKV_M * NPIX + (size_t)(CH + head * DH) * NPIX;
    const float* vp = qkv + (size_t)bi * QKV_M * NPIX + (size_t)(2 * CH + head * DH) * NPIX;

    __shared__ float m_s[DH], z_s[DH];
    int tid = threadIdx.x;
    int warp = tid >> 5, lane = tid & 31;

    for (int r = warp; r < DH; r += 8) {
        const float* row = kp + (size_t)r * NPIX;
        float m = -CUDART_INF_F;
        for (int j = lane; j < NPIX; j += 32) m = fmaxf(m, row[j]);
        #pragma unroll
        for (int o = 16; o; o >>= 1) m = fmaxf(m, __shfl_xor_sync(0xffffffffu, m, o));
        float s = 0.f;
        for (int j = lane; j < NPIX; j += 32) s += __expf(row[j] - m);
        #pragma unroll
        for (int o = 16; o; o >>= 1) s += __shfl_xor_sync(0xffffffffu, s, o);
        if (lane == 0) { m_s[r] = m; z_s[r] = s; }
    }
    __syncthreads();

    __shared__ float kt[DH][129];
    __shared__ float vt[DH][129];
    int e = tid & 31, d8 = tid >> 5;
    float acc[4] = {0.f, 0.f, 0.f, 0.f};

    for (int nn = 0; nn < NPIX; nn += 128) {
        __syncthreads();
        #pragma unroll
        for (int i = 0; i < 16; i++) {
            int idx = tid + i * 256;
            int r = idx >> 7, j = idx & 127;
            kt[r][j] = __expf(kp[(size_t)r * NPIX + nn + j] - m_s[r]);
            vt[r][j] = vp[(size_t)r * NPIX + nn + j];
        }
        __syncthreads();
        #pragma unroll
        for (int j = 0; j < 128; j++) {
            float ve = vt[e][j];
            #pragma unroll
            for (int i = 0; i < 4; i++) acc[i] += kt[d8 + 8 * i][j] * ve;
        }
    }

    float* c = ctx + ((size_t)bi * HEADS + head) * (DH * DH);
    #pragma unroll
    for (int i = 0; i < 4; i++) {
        int d = d8 + 8 * i;
        c[d * DH + e] = acc[i] / z_s[d];
    }
}

// ---------------------------------------------------------------------------
// fused weight -> bf16 hi/lo
// ---------------------------------------------------------------------------
__global__ void __launch_bounds__(256) k_wf(const float* __restrict__ w_out,
                                            const float* __restrict__ ctx,
                                            __nv_bfloat16* __restrict__ wfhi,
                                            __nv_bfloat16* __restrict__ wflo) {
    int head = blockIdx.x, bi = blockIdx.y;
    __shared__ float cs[DH][33];
    int tid = threadIdx.x;
    const float* c = ctx + ((size_t)bi * HEADS + head) * (DH * DH);
    for (int i = tid; i < DH * DH; i += 256) cs[i >> 5][i & 31] = c[i];
    __syncthreads();

    int d = tid & 31, og = tid >> 5;
    for (int o = og; o < CH; o += 8) {
        const float* wrow = w_out + (size_t)o * CH + head * DH;
        float acc = 0.f;
        #pragma unroll
        for (int e = 0; e < DH; e++) acc += wrow[e] * cs[d][e];
        size_t oidx = (size_t)bi * CH * CH + (size_t)o * CH + head * DH + d;
        __nv_bfloat16 h = __float2bfloat16(acc);
        wfhi[oidx] = h;
        wflo[oidx] = __float2bfloat16(acc - __bfloat162float(h));
    }
}

// ---------------------------------------------------------------------------
extern "C" void kernel_launch(void* const* d_in, const int* in_sizes, int n_in,
                              void* d_out, int out_size) {
    const float* x     = (const float*)d_in[0];
    const float* w_qkv = (const float*)d_in[1];
    const float* w_out = (const float*)d_in[2];
    const float* b_out = (const float*)d_in[3];
    float* out = (float*)d_out;

    float *qkv, *ctx;
    __half *xh, *wh, *wl;
    __nv_bfloat16 *qhi, *qlo, *wfhi, *wflo;
    cudaGetSymbolAddress((void**)&qkv,  g_qkv);
    cudaGetSymbolAddress((void**)&ctx,  g_ctx);
    cudaGetSymbolAddress((void**)&xh,   g_xh);
    cudaGetSymbolAddress((void**)&wh,   g_wh);
    cudaGetSymbolAddress((void**)&wl,   g_wl);
    cudaGetSymbolAddress((void**)&qhi,  g_qhi);
    cudaGetSymbolAddress((void**)&qlo,  g_qlo);
    cudaGetSymbolAddress((void**)&wfhi, g_wfhi);
    cudaGetSymbolAddress((void**)&wflo, g_wflo);

    cudaFuncSetAttribute(k_pgemm<false>, cudaFuncAttributeMaxDynamicSharedMemorySize, SMEM_QKV);
    cudaFuncSetAttribute(k_pgemm<true>,  cudaFuncAttributeMaxDynamicSharedMemorySize, SMEM_OUT);

    // 0. splits
    k_split_x<<<(BATCH * CH * FRAMES * NPIX) / 1024, 256>>>(x, xh);
    k_split_w<<<(QKV_M * CH) / 1024, 256>>>(w_qkv, wh, wl);
    // 1. QKV projection: persistent-A, 2-product fp16
    k_pgemm<false><<<dim3(2, QKV_M / 128, BF), 256, SMEM_QKV>>>(
        wh, wl, xh, nullptr, nullptr, qkv);
    // 2. q softmax -> bf16 hi/lo
    k_q_softmax<<<dim3(NPIX / 256, HEADS, BF), 256>>>(qkv, qhi, qlo);
    // 3. k softmax + context
    k_context<<<dim3(HEADS, BF), 256>>>(qkv, ctx);
    // 4. fused weight -> bf16 hi/lo
    k_wf<<<dim3(HEADS, BF), 256>>>(w_out, ctx, wfhi, wflo);
    // 5. output GEMM: persistent-A, 3-product bf16, + bias + scatter
    k_pgemm<true><<<dim3(4, CH / 128, BF), 256, SMEM_OUT>>>(
        wfhi, wflo, qhi, qlo, b_out, out);
}

// round 7
// speedup vs baseline: 2.1122x; 1.0084x over previous
#include <cuda_runtime.h>
#include <cuda_bf16.h>
#include <cuda_fp16.h>
#include <math_constants.h>
#include <cstdint>

// Problem constants
#define BATCH   2
#define CH      256
#define FRAMES  16
#define NPIX    4096
#define BF      32
#define HEADS   8
#define DH      32
#define QKV_M   768
#define XSTRIDE (FRAMES*NPIX)

// ---------------------------------------------------------------------------
// Scratch
// ---------------------------------------------------------------------------
__device__ float g_qkv[(size_t)BF * QKV_M * NPIX];            // only k,v rows used
__device__ float g_ctx[(size_t)BF * HEADS * DH * DH];
__device__ __half g_xh[(size_t)BATCH * CH * FRAMES * NPIX];   // x fp16
__device__ __half g_wh[(size_t)QKV_M * CH];                   // W fp16 hi
__device__ __half g_wl[(size_t)QKV_M * CH];                   // W fp16 lo
__device__ __half g_qh[(size_t)BF * CH * NPIX];               // softmaxed q, fp16
__device__ __half g_wfh[(size_t)BF * CH * CH];                // Wf fp16 hi
__device__ __half g_wfl[(size_t)BF * CH * CH];                // Wf fp16 lo

__device__ __forceinline__ uint32_t smem_u32(const void* p) {
    uint32_t a;
    asm("{ .reg .u64 t; cvta.to.shared.u64 t, %1; cvt.u32.u64 %0, t; }" : "=r"(a) : "l"(p));
    return a;
}
__device__ __forceinline__ void cp16(uint32_t dst, const void* src) {
    asm volatile("cp.async.cg.shared.global [%0], [%1], 16;" :: "r"(dst), "l"(src) : "memory");
}
__device__ __forceinline__ void ldsm4(uint32_t* r, uint32_t addr) {
    asm volatile("ldmatrix.sync.aligned.m8n8.x4.shared.b16 {%0,%1,%2,%3}, [%4];"
                 : "=r"(r[0]), "=r"(r[1]), "=r"(r[2]), "=r"(r[3]) : "r"(addr));
}
__device__ __forceinline__ void ldsm4t(uint32_t* r, uint32_t addr) {
    asm volatile("ldmatrix.sync.aligned.m8n8.x4.trans.shared.b16 {%0,%1,%2,%3}, [%4];"
                 : "=r"(r[0]), "=r"(r[1]), "=r"(r[2]), "=r"(r[3]) : "r"(addr));
}
__device__ __forceinline__ void mma_fp16(float* c, const uint32_t* a, const uint32_t* b) {
    asm volatile("mma.sync.aligned.m16n8k16.row.col.f32.f16.f16.f32 "
                 "{%0,%1,%2,%3}, {%4,%5,%6,%7}, {%8,%9}, {%0,%1,%2,%3};"
                 : "+f"(c[0]), "+f"(c[1]), "+f"(c[2]), "+f"(c[3])
                 : "r"(a[0]), "r"(a[1]), "r"(a[2]), "r"(a[3]), "r"(b[0]), "r"(b[1]));
}

// ---------------------------------------------------------------------------
// Splits
// ---------------------------------------------------------------------------
__global__ void k_split_w(const float* __restrict__ src,
                          __half* __restrict__ hi, __half* __restrict__ lo) {
    size_t i = ((size_t)blockIdx.x * 256 + threadIdx.x) * 4;
    float4 v = *(const float4*)(src + i);
    __half h0 = __float2half(v.x), h1 = __float2half(v.y);
    __half h2 = __float2half(v.z), h3 = __float2half(v.w);
    __half l0 = __float2half(v.x - __half2float(h0));
    __half l1 = __float2half(v.y - __half2float(h1));
    __half l2 = __float2half(v.z - __half2float(h2));
    __half l3 = __float2half(v.w - __half2float(h3));
    __half2* hp = (__half2*)(hi + i);
    __half2* lp = (__half2*)(lo + i);
    hp[0] = __half2(h0, h1); hp[1] = __half2(h2, h3);
    lp[0] = __half2(l0, l1); lp[1] = __half2(l2, l3);
}
__global__ void k_split_x(const float* __restrict__ src, __half* __restrict__ dst) {
    size_t i = ((size_t)blockIdx.x * 256 + threadIdx.x) * 4;
    float4 v = *(const float4*)(src + i);
    __half2* dp = (__half2*)(dst + i);
    dp[0] = __half2(__float2half(v.x), __float2half(v.y));
    dp[1] = __half2(__float2half(v.z), __float2half(v.w));
}

// ---------------------------------------------------------------------------
// Persistent-A 2-product fp16 GEMM (C = (Ah+Al) @ B, fp32 accum).
// A (128 x 256 hi+lo fp16) resident in smem; B streamed, 2-stage cp.async.
// OUT_MODE=false: qkv GEMM. m-tiles 0,1 (q rows): fused softmax-over-d
//                 epilogue -> g_qh fp16. m-tiles 2..5 (k,v): fp32 -> g_qkv.
// OUT_MODE=true : out = Wf @ qh + bias, scatter to (b,c,f,h,w).
// ---------------------------------------------------------------------------
#define PA     528
#define SZ_A   (128 * PA)                 // 67584 per half
#define PB     272
#define SZ_B   (32 * PB)                  // 8704 per stage
#define OFF_B  (2 * SZ_A)                 // 135168
#define GEMM_SMEM (OFF_B + 2 * SZ_B)      // 152576

template <bool OUT_MODE>
__global__ void __launch_bounds__(256, 1) k_pgemm(const __half* __restrict__ Ah_g,
                                                  const __half* __restrict__ Al_g,
                                                  const __half* __restrict__ Bh_g,
                                                  const float* __restrict__ bias,
                                                  float* __restrict__ outp,
                                                  __half* __restrict__ qout) {
    constexpr int NITER = OUT_MODE ? 8 : 16;
    extern __shared__ char smem[];
    const uint32_t sb0 = smem_u32(smem);

    int tid = threadIdx.x, w = tid >> 5, lane = tid & 31;
    int m0 = blockIdx.y * 128;
    int bi = blockIdx.z, b = bi >> 4, f = bi & 15;
    int n_start = blockIdx.x * NITER * 128;
    const bool Q_TILE = !OUT_MODE && (blockIdx.y < 2);

    const __half* Ah = Ah_g + (OUT_MODE ? (size_t)bi * CH * CH : 0);
    const __half* Al = Al_g + (OUT_MODE ? (size_t)bi * CH * CH : 0);
    const size_t bstride = OUT_MODE ? (size_t)NPIX : (size_t)XSTRIDE;
    const __half* Bh = Bh_g + (OUT_MODE ? (size_t)bi * CH * NPIX
                                        : ((size_t)(b * CH) * FRAMES + f) * NPIX);

    // ---- load A (full K, hi+lo) once ----
    #pragma unroll
    for (int i = 0; i < 16; i++) {
        int ch = tid + i * 256;
        int r = ch >> 5, c = ch & 31;
        size_t goff = (size_t)(m0 + r) * CH + c * 8;
        uint32_t d = sb0 + r * PA + c * 16;
        cp16(d, Ah + goff);
        cp16(d + SZ_A, Al + goff);
    }
    asm volatile("cp.async.commit_group;" ::: "memory");

    auto loadB = [&](int c) {
        int nt = c >> 3, kt = c & 7;
        int nb = n_start + nt * 128;
        uint32_t sb = sb0 + OFF_B + (uint32_t)(c & 1) * SZ_B;
        #pragma unroll
        for (int i = 0; i < 2; i++) {
            int ch = tid + i * 256;
            int r = ch >> 4, cc = ch & 15;
            cp16(sb + r * PB + cc * 16,
                 Bh + (size_t)(kt * 32 + r) * bstride + nb + cc * 8);
        }
        asm volatile("cp.async.commit_group;" ::: "memory");
    };

    int wm = (w & 1) * 64;
    int wn = (w >> 1) * 32;
    uint32_t aAddr = sb0 + (uint32_t)(wm + (lane & 15)) * PA + (uint32_t)(lane >> 4) * 16;
    uint32_t bAddr = (uint32_t)(lane & 15) * PB + (uint32_t)(lane >> 4) * 16
                   + (uint32_t)wn * 2;

    loadB(0);
    const int C = NITER * 8;

    for (int nt = 0; nt < NITER; nt++) {
        float acc[4][4][4];
        #pragma unroll
        for (int i = 0; i < 4; i++)
            #pragma unroll
            for (int j = 0; j < 4; j++)
                #pragma unroll
                for (int r = 0; r < 4; r++) acc[i][j][r] = 0.f;

        for (int kt = 0; kt < 8; kt++) {
            int c = nt * 8 + kt;
            if (c + 1 < C) loadB(c + 1);
            else asm volatile("cp.async.commit_group;" ::: "memory");
            asm volatile("cp.async.wait_group %0;" :: "n"(1) : "memory");
            __syncthreads();

            uint32_t sb = sb0 + OFF_B + (uint32_t)(c & 1) * SZ_B;
            #pragma unroll
            for (int ks = 0; ks < 2; ks++) {
                uint32_t aHf[4][4], aLf[4][4], bHf[2][4];
                #pragma unroll
                for (int mi = 0; mi < 4; mi++) {
                    uint32_t ad = aAddr + (uint32_t)(mi * 16) * PA + kt * 64 + ks * 32;
                    ldsm4(aHf[mi], ad);
                    ldsm4(aLf[mi], ad + SZ_A);
                }
                #pragma unroll
                for (int ng = 0; ng < 2; ng++) {
                    uint32_t bd = sb + bAddr + (uint32_t)(ks * 16) * PB + ng * 32;
                    ldsm4t(bHf[ng], bd);
                }
                #pragma unroll
                for (int mi = 0; mi < 4; mi++)
                    #pragma unroll
                    for (int ni = 0; ni < 4; ni++) {
                        const uint32_t* bh = &bHf[ni >> 1][(ni & 1) * 2];
                        mma_fp16(acc[mi][ni], aHf[mi], bh);
                        mma_fp16(acc[mi][ni], aLf[mi], bh);
                    }
            }
            __syncthreads();
        }

        int n0 = n_start + nt * 128;
        if (Q_TILE) {
            // ---- fused softmax over d (per head = 2 mi pairs), store fp16 ----
            // column set per thread: ni in 0..3, parity p in {0,1};
            // d-values: regs {mi0,p},{mi0,p+2},{mi1,p},{mi1,p+2} + lanes xor 4,8,16
            #pragma unroll
            for (int h = 0; h < 2; h++) {
                int mi0 = 2 * h, mi1 = 2 * h + 1;
                #pragma unroll
                for (int ni = 0; ni < 4; ni++) {
                    #pragma unroll
                    for (int p = 0; p < 2; p++) {
                        float v0 = acc[mi0][ni][p],     v1 = acc[mi0][ni][p + 2];
                        float v2 = acc[mi1][ni][p],     v3 = acc[mi1][ni][p + 2];
                        float mx = fmaxf(fmaxf(v0, v1), fmaxf(v2, v3));
                        mx = fmaxf(mx, __shfl_xor_sync(0xffffffffu, mx, 4));
                        mx = fmaxf(mx, __shfl_xor_sync(0xffffffffu, mx, 8));
                        mx = fmaxf(mx, __shfl_xor_sync(0xffffffffu, mx, 16));
                        v0 = __expf(v0 - mx); v1 = __expf(v1 - mx);
                        v2 = __expf(v2 - mx); v3 = __expf(v3 - mx);
                        float s = v0 + v1 + v2 + v3;
                        s += __shfl_xor_sync(0xffffffffu, s, 4);
                        s += __shfl_xor_sync(0xffffffffu, s, 8);
                        s += __shfl_xor_sync(0xffffffffu, s, 16);
                        float inv = 0.17677669529663687f / s;
                        acc[mi0][ni][p]     = v0 * inv;
                        acc[mi0][ni][p + 2] = v1 * inv;
                        acc[mi1][ni][p]     = v2 * inv;
                        acc[mi1][ni][p + 2] = v3 * inv;
                    }
                }
            }
            __half* qbase = qout + (size_t)bi * CH * NPIX;
            #pragma unroll
            for (int mi = 0; mi < 4; mi++) {
                #pragma unroll
                for (int ni = 0; ni < 4; ni++) {
                    int r0 = m0 + wm + mi * 16 + (lane >> 2);
                    int r1 = r0 + 8;
                    int cc = n0 + wn + ni * 8 + (lane & 3) * 2;
                    *(__half2*)(qbase + (size_t)r0 * NPIX + cc) =
                        __half2(__float2half(acc[mi][ni][0]), __float2half(acc[mi][ni][1]));
                    *(__half2*)(qbase + (size_t)r1 * NPIX + cc) =
                        __half2(__float2half(acc[mi][ni][2]), __float2half(acc[mi][ni][3]));
                }
            }
        } else {
            #pragma unroll
            for (int mi = 0; mi < 4; mi++) {
                #pragma unroll
                for (int ni = 0; ni < 4; ni++) {
                    int r0 = m0 + wm + mi * 16 + (lane >> 2);
                    int r1 = r0 + 8;
                    int cc = n0 + wn + ni * 8 + (lane & 3) * 2;
                    if (OUT_MODE) {
                        float b0 = bias[r0], b1 = bias[r1];
                        float* p0 = outp + ((size_t)(b * CH + r0) * FRAMES + f) * NPIX + cc;
                        float* p1 = outp + ((size_t)(b * CH + r1) * FRAMES + f) * NPIX + cc;
                        *(float2*)p0 = make_float2(acc[mi][ni][0] + b0, acc[mi][ni][1] + b0);
                        *(float2*)p1 = make_float2(acc[mi][ni][2] + b1, acc[mi][ni][3] + b1);
                    } else {
                        float* p0 = outp + (size_t)bi * QKV_M * NPIX + (size_t)r0 * NPIX + cc;
                        float* p1 = outp + (size_t)bi * QKV_M * NPIX + (size_t)r1 * NPIX + cc;
                        *(float2*)p0 = make_float2(acc[mi][ni][0], acc[mi][ni][1]);
                        *(float2*)p1 = make_float2(acc[mi][ni][2], acc[mi][ni][3]);
                    }
                }
            }
        }
    }
}

// ---------------------------------------------------------------------------
// k softmax over n fused with context[d][e] = sum_n k_sm[d,n]*v[e,n]
// ---------------------------------------------------------------------------
__global__ void __launch_bounds__(256) k_context(const float* __restrict__ qkv,
                                                 float* __restrict__ ctx) {
    int head = blockIdx.x, bi = blockIdx.y;
    const float* kp = qkv + (size_t)bi * QKV_M * NPIX + (size_t)(CH + head * DH) * NPIX;
    const float* vp = qkv + (size_t)bi * QKV_M * NPIX + (size_t)(2 * CH + head * DH) * NPIX;

    __shared__ float m_s[DH], z_s[DH];
    int tid = threadIdx.x;
    int warp = tid >> 5, lane = tid & 31;

    for (int r = warp; r < DH; r += 8) {
        const float* row = kp + (size_t)r * NPIX;
        float m = -CUDART_INF_F;
        for (int j = lane; j < NPIX; j += 32) m = fmaxf(m, row[j]);
        #pragma unroll
        for (int o = 16; o; o >>= 1) m = fmaxf(m, __shfl_xor_sync(0xffffffffu, m, o));
        float s = 0.f;
        for (int j = lane; j < NPIX; j += 32) s += __expf(row[j] - m);
        #pragma unroll
        for (int o = 16; o; o >>= 1) s += __shfl_xor_sync(0xffffffffu, s, o);
        if (lane == 0) { m_s[r] = m; z_s[r] = s; }
    }
    __syncthreads();

    __shared__ float kt[DH][129];
    __shared__ float vt[DH][129];
    int e = tid & 31, d8 = tid >> 5;
    float acc[4] = {0.f, 0.f, 0.f, 0.f};

    for (int nn = 0; nn < NPIX; nn += 128) {
        __syncthreads();
        #pragma unroll
        for (int i = 0; i < 16; i++) {
            int idx = tid + i * 256;
            int r = idx >> 7, j = idx & 127;
            kt[r][j] = __expf(kp[(size_t)r * NPIX + nn + j] - m_s[r]);
            vt[r][j] = vp[(size_t)r * NPIX + nn + j];
        }
        __syncthreads();
        #pragma unroll
        for (int j = 0; j < 128; j++) {
            float ve = vt[e][j];
            #pragma unroll
            for (int i = 0; i < 4; i++) acc[i] += kt[d8 + 8 * i][j] * ve;
        }
    }

    float* c = ctx + ((size_t)bi * HEADS + head) * (DH * DH);
    #pragma unroll
    for (int i = 0; i < 4; i++) {
        int d = d8 + 8 * i;
        c[d * DH + e] = acc[i] / z_s[d];
    }
}

// ---------------------------------------------------------------------------
// fused weight Wf -> fp16 hi/lo
// ---------------------------------------------------------------------------
__global__ void __launch_bounds__(256) k_wf(const float* __restrict__ w_out,
                                            const float* __restrict__ ctx,
                                            __half* __restrict__ wfh,
                                            __half* __restrict__ wfl) {
    int head = blockIdx.x, bi = blockIdx.y;
    __shared__ float cs[DH][33];
    int tid = threadIdx.x;
    const float* c = ctx + ((size_t)bi * HEADS + head) * (DH * DH);
    for (int i = tid; i < DH * DH; i += 256) cs[i >> 5][i & 31] = c[i];
    __syncthreads();

    int d = tid & 31, og = tid >> 5;
    for (int o = og; o < CH; o += 8) {
        const float* wrow = w_out + (size_t)o * CH + head * DH;
        float acc = 0.f;
        #pragma unroll
        for (int e = 0; e < DH; e++) acc += wrow[e] * cs[d][e];
        size_t oidx = (size_t)bi * CH * CH + (size_t)o * CH + head * DH + d;
        __half h = __float2half(acc);
        wfh[oidx] = h;
        wfl[oidx] = __float2half(acc - __half2float(h));
    }
}

// ---------------------------------------------------------------------------
extern "C" void kernel_launch(void* const* d_in, const int* in_sizes, int n_in,
                              void* d_out, int out_size) {
    const float* x     = (const float*)d_in[0];
    const float* w_qkv = (const float*)d_in[1];
    const float* w_out = (const float*)d_in[2];
    const float* b_out = (const float*)d_in[3];
    float* out = (float*)d_out;

    float *qkv, *ctx;
    __half *xh, *wh, *wl, *qh, *wfh, *wfl;
    cudaGetSymbolAddress((void**)&qkv, g_qkv);
    cudaGetSymbolAddress((void**)&ctx, g_ctx);
    cudaGetSymbolAddress((void**)&xh,  g_xh);
    cudaGetSymbolAddress((void**)&wh,  g_wh);
    cudaGetSymbolAddress((void**)&wl,  g_wl);
    cudaGetSymbolAddress((void**)&qh,  g_qh);
    cudaGetSymbolAddress((void**)&wfh, g_wfh);
    cudaGetSymbolAddress((void**)&wfl, g_wfl);

    cudaFuncSetAttribute(k_pgemm<false>, cudaFuncAttributeMaxDynamicSharedMemorySize, GEMM_SMEM);
    cudaFuncSetAttribute(k_pgemm<true>,  cudaFuncAttributeMaxDynamicSharedMemorySize, GEMM_SMEM);

    // 0. splits
    k_split_x<<<(BATCH * CH * FRAMES * NPIX) / 1024, 256>>>(x, xh);
    k_split_w<<<(QKV_M * CH) / 1024, 256>>>(w_qkv, wh, wl);
    // 1. QKV GEMM; q m-tiles get fused softmax-over-d -> g_qh fp16
    k_pgemm<false><<<dim3(2, QKV_M / 128, BF), 256, GEMM_SMEM>>>(
        wh, wl, xh, nullptr, qkv, qh);
    // 2. k softmax + context
    k_context<<<dim3(HEADS, BF), 256>>>(qkv, ctx);
    // 3. fused weight -> fp16 hi/lo
    k_wf<<<dim3(HEADS, BF), 256>>>(w_out, ctx, wfh, wfl);
    // 4. output GEMM (2-product fp16) + bias + scatter
    k_pgemm<true><<<dim3(4, CH / 128, BF), 256, GEMM_SMEM>>>(
        wfh, wfl, qh, b_out, out, nullptr);
}

// round 9
// speedup vs baseline: 3.0828x; 1.4595x over previous
#include <cuda_runtime.h>
#include <cuda_bf16.h>
#include <cuda_fp16.h>
#include <math_constants.h>
#include <cstdint>

// Problem constants
#define BATCH   2
#define CH      256
#define FRAMES  16
#define NPIX    4096
#define BF      32
#define HEADS   8
#define DH      32
#define QKV_M   768
#define XSTRIDE (FRAMES*NPIX)
#define CHUNKS  4
#define CK_N    1024     // n per context chunk

// ---------------------------------------------------------------------------
// Scratch
// ---------------------------------------------------------------------------
__device__ __half g_xh[(size_t)BATCH * CH * FRAMES * NPIX];   // x fp16
__device__ __half g_wh[(size_t)QKV_M * CH];
__device__ __half g_wl[(size_t)QKV_M * CH];
__device__ __half g_qh[(size_t)BF * CH * NPIX];               // softmaxed q fp16
__device__ float  g_kf[(size_t)BF * CH * NPIX];               // k fp32
__device__ __half g_vh[(size_t)BF * CH * NPIX];               // v fp16 hi
__device__ __half g_vl[(size_t)BF * CH * NPIX];               // v fp16 lo
__device__ float  g_ctxp[(size_t)CHUNKS * BF * HEADS * DH * DH];
__device__ float  g_zp[(size_t)CHUNKS * BF * HEADS * DH];
__device__ __half g_wfh[(size_t)BF * CH * CH];
__device__ __half g_wfl[(size_t)BF * CH * CH];

__device__ __forceinline__ uint32_t smem_u32(const void* p) {
    uint32_t a;
    asm("{ .reg .u64 t; cvta.to.shared.u64 t, %1; cvt.u32.u64 %0, t; }" : "=r"(a) : "l"(p));
    return a;
}
__device__ __forceinline__ void cp16(uint32_t dst, const void* src) {
    asm volatile("cp.async.cg.shared.global [%0], [%1], 16;" :: "r"(dst), "l"(src) : "memory");
}
__device__ __forceinline__ void ldsm4(uint32_t* r, uint32_t addr) {
    asm volatile("ldmatrix.sync.aligned.m8n8.x4.shared.b16 {%0,%1,%2,%3}, [%4];"
                 : "=r"(r[0]), "=r"(r[1]), "=r"(r[2]), "=r"(r[3]) : "r"(addr));
}
__device__ __forceinline__ void ldsm4t(uint32_t* r, uint32_t addr) {
    asm volatile("ldmatrix.sync.aligned.m8n8.x4.trans.shared.b16 {%0,%1,%2,%3}, [%4];"
                 : "=r"(r[0]), "=r"(r[1]), "=r"(r[2]), "=r"(r[3]) : "r"(addr));
}
__device__ __forceinline__ void mma_fp16(float* c, const uint32_t* a, const uint32_t* b) {
    asm volatile("mma.sync.aligned.m16n8k16.row.col.f32.f16.f16.f32 "
                 "{%0,%1,%2,%3}, {%4,%5,%6,%7}, {%8,%9}, {%0,%1,%2,%3};"
                 : "+f"(c[0]), "+f"(c[1]), "+f"(c[2]), "+f"(c[3])
                 : "r"(a[0]), "r"(a[1]), "r"(a[2]), "r"(a[3]), "r"(b[0]), "r"(b[1]));
}
__device__ __forceinline__ void mma_fp16_2(float* c, const uint32_t* a,
                                           uint32_t b0, uint32_t b1) {
    asm volatile("mma.sync.aligned.m16n8k16.row.col.f32.f16.f16.f32 "
                 "{%0,%1,%2,%3}, {%4,%5,%6,%7}, {%8,%9}, {%0,%1,%2,%3};"
                 : "+f"(c[0]), "+f"(c[1]), "+f"(c[2]), "+f"(c[3])
                 : "r"(a[0]), "r"(a[1]), "r"(a[2]), "r"(a[3]), "r"(b0), "r"(b1));
}

// ---------------------------------------------------------------------------
// Splits
// ---------------------------------------------------------------------------
__global__ void k_split_w(const float* __restrict__ src,
                          __half* __restrict__ hi, __half* __restrict__ lo) {
    size_t i = ((size_t)blockIdx.x * 256 + threadIdx.x) * 4;
    float4 v = *(const float4*)(src + i);
    __half h0 = __float2half(v.x), h1 = __float2half(v.y);
    __half h2 = __float2half(v.z), h3 = __float2half(v.w);
    __half l0 = __float2half(v.x - __half2float(h0));
    __half l1 = __float2half(v.y - __half2float(h1));
    __half l2 = __float2half(v.z - __half2float(h2));
    __half l3 = __float2half(v.w - __half2float(h3));
    __half2* hp = (__half2*)(hi + i);
    __half2* lp = (__half2*)(lo + i);
    hp[0] = __half2(h0, h1); hp[1] = __half2(h2, h3);
    lp[0] = __half2(l0, l1); lp[1] = __half2(l2, l3);
}
__global__ void k_split_x(const float* __restrict__ src, __half* __restrict__ dst) {
    size_t i = ((size_t)blockIdx.x * 256 + threadIdx.x) * 4;
    float4 v = *(const float4*)(src + i);
    __half2* dp = (__half2*)(dst + i);
    dp[0] = __half2(__float2half(v.x), __float2half(v.y));
    dp[1] = __half2(__float2half(v.z), __float2half(v.w));
}

// ---------------------------------------------------------------------------
// Persistent-A 2-product fp16 GEMM (C = (Ah+Al) @ B, fp32 accum).
// OUT_MODE=false: qkv GEMM. m-tiles 0,1 (q): fused softmax -> g_qh fp16.
//                 m-tiles 2,3 (k): fp32 -> g_kf.  m-tiles 4,5 (v): fp16 hi/lo.
// OUT_MODE=true : out = Wf @ qh + bias, scatter to (b,c,f,h,w).
// ---------------------------------------------------------------------------
#define PA     528
#define SZ_A   (128 * PA)
#define PB     272
#define SZ_B   (32 * PB)
#define OFF_B  (2 * SZ_A)
#define GEMM_SMEM (OFF_B + 2 * SZ_B)

template <bool OUT_MODE>
__global__ void __launch_bounds__(256, 1) k_pgemm(const __half* __restrict__ Ah_g,
                                                  const __half* __restrict__ Al_g,
                                                  const __half* __restrict__ Bh_g,
                                                  const float* __restrict__ bias,
                                                  float* __restrict__ outp,
                                                  __half* __restrict__ qout,
                                                  float* __restrict__ kout,
                                                  __half* __restrict__ vhout,
                                                  __half* __restrict__ vlout) {
    constexpr int NITER = OUT_MODE ? 8 : 16;
    extern __shared__ char smem[];
    const uint32_t sb0 = smem_u32(smem);

    int tid = threadIdx.x, w = tid >> 5, lane = tid & 31;
    int m0 = blockIdx.y * 128;
    int bi = blockIdx.z, b = bi >> 4, f = bi & 15;
    int n_start = blockIdx.x * NITER * 128;
    const int TILE_KIND = OUT_MODE ? 3 : (int)(blockIdx.y >> 1);  // 0=q,1=k,2=v,3=out

    const __half* Ah = Ah_g + (OUT_MODE ? (size_t)bi * CH * CH : 0);
    const __half* Al = Al_g + (OUT_MODE ? (size_t)bi * CH * CH : 0);
    const size_t bstride = OUT_MODE ? (size_t)NPIX : (size_t)XSTRIDE;
    const __half* Bh = Bh_g + (OUT_MODE ? (size_t)bi * CH * NPIX
                                        : ((size_t)(b * CH) * FRAMES + f) * NPIX);

    #pragma unroll
    for (int i = 0; i < 16; i++) {
        int ch = tid + i * 256;
        int r = ch >> 5, c = ch & 31;
        size_t goff = (size_t)(m0 + r) * CH + c * 8;
        uint32_t d = sb0 + r * PA + c * 16;
        cp16(d, Ah + goff);
        cp16(d + SZ_A, Al + goff);
    }
    asm volatile("cp.async.commit_group;" ::: "memory");

    auto loadB = [&](int c) {
        int nt = c >> 3, kt = c & 7;
        int nb = n_start + nt * 128;
        uint32_t sb = sb0 + OFF_B + (uint32_t)(c & 1) * SZ_B;
        #pragma unroll
        for (int i = 0; i < 2; i++) {
            int ch = tid + i * 256;
            int r = ch >> 4, cc = ch & 15;
            cp16(sb + r * PB + cc * 16,
                 Bh + (size_t)(kt * 32 + r) * bstride + nb + cc * 8);
        }
        asm volatile("cp.async.commit_group;" ::: "memory");
    };

    int wm = (w & 1) * 64;
    int wn = (w >> 1) * 32;
    uint32_t aAddr = sb0 + (uint32_t)(wm + (lane & 15)) * PA + (uint32_t)(lane >> 4) * 16;
    uint32_t bAddr = (uint32_t)(lane & 15) * PB + (uint32_t)(lane >> 4) * 16
                   + (uint32_t)wn * 2;

    loadB(0);
    const int C = NITER * 8;

    for (int nt = 0; nt < NITER; nt++) {
        float acc[4][4][4];
        #pragma unroll
        for (int i = 0; i < 4; i++)
            #pragma unroll
            for (int j = 0; j < 4; j++)
                #pragma unroll
                for (int r = 0; r < 4; r++) acc[i][j][r] = 0.f;

        for (int kt = 0; kt < 8; kt++) {
            int c = nt * 8 + kt;
            if (c + 1 < C) loadB(c + 1);
            else asm volatile("cp.async.commit_group;" ::: "memory");
            asm volatile("cp.async.wait_group %0;" :: "n"(1) : "memory");
            __syncthreads();

            uint32_t sb = sb0 + OFF_B + (uint32_t)(c & 1) * SZ_B;
            #pragma unroll
            for (int ks = 0; ks < 2; ks++) {
                uint32_t aHf[4][4], aLf[4][4], bHf[2][4];
                #pragma unroll
                for (int mi = 0; mi < 4; mi++) {
                    uint32_t ad = aAddr + (uint32_t)(mi * 16) * PA + kt * 64 + ks * 32;
                    ldsm4(aHf[mi], ad);
                    ldsm4(aLf[mi], ad + SZ_A);
                }
                #pragma unroll
                for (int ng = 0; ng < 2; ng++) {
                    uint32_t bd = sb + bAddr + (uint32_t)(ks * 16) * PB + ng * 32;
                    ldsm4t(bHf[ng], bd);
                }
                #pragma unroll
                for (int mi = 0; mi < 4; mi++)
                    #pragma unroll
                    for (int ni = 0; ni < 4; ni++) {
                        const uint32_t* bh = &bHf[ni >> 1][(ni & 1) * 2];
                        mma_fp16(acc[mi][ni], aHf[mi], bh);
                        mma_fp16(acc[mi][ni], aLf[mi], bh);
                    }
            }
            __syncthreads();
        }

        int n0 = n_start + nt * 128;
        if (TILE_KIND == 0) {
            // fused softmax over d, store fp16 q
            #pragma unroll
            for (int h = 0; h < 2; h++) {
                int mi0 = 2 * h, mi1 = 2 * h + 1;
                #pragma unroll
                for (int ni = 0; ni < 4; ni++) {
                    #pragma unroll
                    for (int p = 0; p < 2; p++) {
                        float v0 = acc[mi0][ni][p],     v1 = acc[mi0][ni][p + 2];
                        float v2 = acc[mi1][ni][p],     v3 = acc[mi1][ni][p + 2];
                        float mx = fmaxf(fmaxf(v0, v1), fmaxf(v2, v3));
                        mx = fmaxf(mx, __shfl_xor_sync(0xffffffffu, mx, 4));
                        mx = fmaxf(mx, __shfl_xor_sync(0xffffffffu, mx, 8));
                        mx = fmaxf(mx, __shfl_xor_sync(0xffffffffu, mx, 16));
                        v0 = __expf(v0 - mx); v1 = __expf(v1 - mx);
                        v2 = __expf(v2 - mx); v3 = __expf(v3 - mx);
                        float s = v0 + v1 + v2 + v3;
                        s += __shfl_xor_sync(0xffffffffu, s, 4);
                        s += __shfl_xor_sync(0xffffffffu, s, 8);
                        s += __shfl_xor_sync(0xffffffffu, s, 16);
                        float inv = 0.17677669529663687f / s;
                        acc[mi0][ni][p]     = v0 * inv;
                        acc[mi0][ni][p + 2] = v1 * inv;
                        acc[mi1][ni][p]     = v2 * inv;
                        acc[mi1][ni][p + 2] = v3 * inv;
                    }
                }
            }
            __half* qbase = qout + (size_t)bi * CH * NPIX;
            #pragma unroll
            for (int mi = 0; mi < 4; mi++)
                #pragma unroll
                for (int ni = 0; ni < 4; ni++) {
                    int r0 = m0 + wm + mi * 16 + (lane >> 2);
                    int cc = n0 + wn + ni * 8 + (lane & 3) * 2;
                    *(__half2*)(qbase + (size_t)r0 * NPIX + cc) =
                        __half2(__float2half(acc[mi][ni][0]), __float2half(acc[mi][ni][1]));
                    *(__half2*)(qbase + (size_t)(r0 + 8) * NPIX + cc) =
                        __half2(__float2half(acc[mi][ni][2]), __float2half(acc[mi][ni][3]));
                }
        } else if (TILE_KIND == 1) {
            // k: fp32
            float* kbase = kout + (size_t)bi * CH * NPIX;
            #pragma unroll
            for (int mi = 0; mi < 4; mi++)
                #pragma unroll
                for (int ni = 0; ni < 4; ni++) {
                    int r0 = m0 - 256 + wm + mi * 16 + (lane >> 2);
                    int cc = n0 + wn + ni * 8 + (lane & 3) * 2;
                    *(float2*)(kbase + (size_t)r0 * NPIX + cc) =
                        make_float2(acc[mi][ni][0], acc[mi][ni][1]);
                    *(float2*)(kbase + (size_t)(r0 + 8) * NPIX + cc) =
                        make_float2(acc[mi][ni][2], acc[mi][ni][3]);
                }
        } else if (TILE_KIND == 2) {
            // v: fp16 hi/lo
            __half* vhb = vhout + (size_t)bi * CH * NPIX;
            __half* vlb = vlout + (size_t)bi * CH * NPIX;
            #pragma unroll
            for (int mi = 0; mi < 4; mi++)
                #pragma unroll
                for (int ni = 0; ni < 4; ni++) {
                    int r0 = m0 - 512 + wm + mi * 16 + (lane >> 2);
                    int cc = n0 + wn + ni * 8 + (lane & 3) * 2;
                    #pragma unroll
                    for (int rr = 0; rr < 2; rr++) {
                        float a0 = acc[mi][ni][rr * 2], a1 = acc[mi][ni][rr * 2 + 1];
                        __half h0 = __float2half(a0), h1 = __float2half(a1);
                        __half l0 = __float2half(a0 - __half2float(h0));
                        __half l1 = __float2half(a1 - __half2float(h1));
                        size_t off = (size_t)(r0 + rr * 8) * NPIX + cc;
                        *(__half2*)(vhb + off) = __half2(h0, h1);
                        *(__half2*)(vlb + off) = __half2(l0, l1);
                    }
                }
        } else {
            // out: + bias, scatter
            #pragma unroll
            for (int mi = 0; mi < 4; mi++)
                #pragma unroll
                for (int ni = 0; ni < 4; ni++) {
                    int r0 = m0 + wm + mi * 16 + (lane >> 2);
                    int r1 = r0 + 8;
                    int cc = n0 + wn + ni * 8 + (lane & 3) * 2;
                    float b0 = bias[r0], b1 = bias[r1];
                    float* p0 = outp + ((size_t)(b * CH + r0) * FRAMES + f) * NPIX + cc;
                    float* p1 = outp + ((size_t)(b * CH + r1) * FRAMES + f) * NPIX + cc;
                    *(float2*)p0 = make_float2(acc[mi][ni][0] + b0, acc[mi][ni][1] + b0);
                    *(float2*)p1 = make_float2(acc[mi][ni][2] + b1, acc[mi][ni][3] + b1);
                }
        }
    }
}

// ---------------------------------------------------------------------------
// Tensor-core context: P[d][e] = sum_n exp(k[d,n]) * v[e,n], z[d] = sum exp.
// Grid (HEADS, BF, CHUNKS). 8 warps; per 128-col pass each warp owns one
// K=16 step. S = exp(k) in fp16 hi/lo; 3-product mma. Partials to gmem.
// ---------------------------------------------------------------------------
#define CKP   528                       // k tile pitch (128 fp32 + pad)
#define CKSZ  (32 * CKP)                // 16896 per stage
#define CVP   272                       // v/s pitch (128 fp16 + pad)
#define CVSZ  (32 * CVP)                // 8704 per half
#define COFFV (2 * CKSZ)                // 33792
#define COFFS (COFFV + 2 * 2 * CVSZ)    // 68608
#define COFFZ (COFFS + 2 * CVSZ)        // 86016
#define CTX_SMEM (COFFZ + 1024)         // 87040

__global__ void __launch_bounds__(256, 2) k_context_tc(const float* __restrict__ kf,
                                                       const __half* __restrict__ vh,
                                                       const __half* __restrict__ vl,
                                                       float* __restrict__ ctxp,
                                                       float* __restrict__ zp) {
    extern __shared__ char smem[];
    const uint32_t sb0 = smem_u32(smem);
    int tid = threadIdx.x, w = tid >> 5, lane = tid & 31;
    int head = blockIdx.x, bi = blockIdx.y, chunk = blockIdx.z;
    int bh = bi * HEADS + head;

    const float*  kbase = kf + ((size_t)bi * CH + head * DH) * NPIX + chunk * CK_N;
    const __half* vhb   = vh + ((size_t)bi * CH + head * DH) * NPIX + chunk * CK_N;
    const __half* vlb   = vl + ((size_t)bi * CH + head * DH) * NPIX + chunk * CK_N;

    auto loadT = [&](int p) {
        int st = p & 1;
        int n0 = p * 128;
        uint32_t kd = sb0 + st * CKSZ;
        #pragma unroll
        for (int i = 0; i < 4; i++) {
            int ch = tid + i * 256;
            int r = ch >> 5, c = ch & 31;
            cp16(kd + r * CKP + c * 16, kbase + (size_t)r * NPIX + n0 + c * 4);
        }
        uint32_t vd = sb0 + COFFV + st * (2 * CVSZ);
        #pragma unroll
        for (int i = 0; i < 2; i++) {
            int ch = tid + i * 256;
            int r = ch >> 4, c = ch & 15;
            size_t go = (size_t)r * NPIX + n0 + c * 8;
            cp16(vd + r * CVP + c * 16, vhb + go);
            cp16(vd + CVSZ + r * CVP + c * 16, vlb + go);
        }
        asm volatile("cp.async.commit_group;" ::: "memory");
    };

    float acc[2][4][4];
    #pragma unroll
    for (int i = 0; i < 2; i++)
        #pragma unroll
        for (int j = 0; j < 4; j++)
            #pragma unroll
            for (int r = 0; r < 4; r++) acc[i][j][r] = 0.f;
    float zacc = 0.f;

    int crow = tid >> 3, cseg = tid & 7;     // conversion: fixed row per thread

    loadT(0);
    for (int p = 0; p < 8; p++) {
        if (p + 1 < 8) loadT(p + 1);
        else asm volatile("cp.async.commit_group;" ::: "memory");
        asm volatile("cp.async.wait_group %0;" :: "n"(1) : "memory");
        __syncthreads();

        // convert: 16 fp32 per thread -> exp -> fp16 hi/lo into S
        {
            const float* krow = (const float*)(smem + (p & 1) * CKSZ + crow * CKP) + cseg * 16;
            uint32_t hv[8], lv[8];
            #pragma unroll
            for (int j = 0; j < 8; j++) {
                float e0 = __expf(krow[2 * j]);
                float e1 = __expf(krow[2 * j + 1]);
                zacc += e0 + e1;
                __half h0 = __float2half(e0), h1 = __float2half(e1);
                __half l0 = __float2half(e0 - __half2float(h0));
                __half l1 = __float2half(e1 - __half2float(h1));
                hv[j] = (uint32_t)__half_as_ushort(h0) | ((uint32_t)__half_as_ushort(h1) << 16);
                lv[j] = (uint32_t)__half_as_ushort(l0) | ((uint32_t)__half_as_ushort(l1) << 16);
            }
            uint32_t sd = sb0 + COFFS + crow * CVP + cseg * 32;
            asm volatile("st.shared.v4.b32 [%0], {%1,%2,%3,%4};"
                         :: "r"(sd), "r"(hv[0]), "r"(hv[1]), "r"(hv[2]), "r"(hv[3]) : "memory");
            asm volatile("st.shared.v4.b32 [%0], {%1,%2,%3,%4};"
                         :: "r"(sd + 16), "r"(hv[4]), "r"(hv[5]), "r"(hv[6]), "r"(hv[7]) : "memory");
            asm volatile("st.shared.v4.b32 [%0], {%1,%2,%3,%4};"
                         :: "r"(sd + CVSZ), "r"(lv[0]), "r"(lv[1]), "r"(lv[2]), "r"(lv[3]) : "memory");
            asm volatile("st.shared.v4.b32 [%0], {%1,%2,%3,%4};"
                         :: "r"(sd + CVSZ + 16), "r"(lv[4]), "r"(lv[5]), "r"(lv[6]), "r"(lv[7]) : "memory");
        }
        __syncthreads();

        // mma: warp w owns cols w*16..w*16+15 of this 128-col tile
        {
            uint32_t cb = (uint32_t)w * 32 + (uint32_t)(lane >> 4) * 16;
            uint32_t sh[2][4], sl[2][4];
            #pragma unroll
            for (int mi = 0; mi < 2; mi++) {
                uint32_t sa = sb0 + COFFS + (uint32_t)(mi * 16 + (lane & 15)) * CVP + cb;
                ldsm4(sh[mi], sa);
                ldsm4(sl[mi], sa + CVSZ);
            }
            uint32_t vbase = sb0 + COFFV + (uint32_t)(p & 1) * (2 * CVSZ);
            #pragma unroll
            for (int ei = 0; ei < 2; ei++) {
                uint32_t vhf[4], vlf[4];
                uint32_t va = vbase + (uint32_t)(ei * 16 + (lane & 15)) * CVP + cb;
                ldsm4(vhf, va);
                ldsm4(vlf, va + CVSZ);
                #pragma unroll
                for (int pick = 0; pick < 2; pick++) {
                    int nt = ei * 2 + pick;
                    #pragma unroll
                    for (int mi = 0; mi < 2; mi++) {
                        mma_fp16_2(acc[mi][nt], sh[mi], vhf[pick], vhf[pick + 2]);
                        mma_fp16_2(acc[mi][nt], sl[mi], vhf[pick], vhf[pick + 2]);
                        mma_fp16_2(acc[mi][nt], sh[mi], vlf[pick], vlf[pick + 2]);
                    }
                }
            }
        }
        __syncthreads();
    }

    // ---- reduce across 8 warps ----
    float* stage = (float*)(smem) + w * 1056;   // 32 x 33 per warp, overlays k bufs
    #pragma unroll
    for (int mi = 0; mi < 2; mi++)
        #pragma unroll
        for (int nt = 0; nt < 4; nt++) {
            int r0 = mi * 16 + (lane >> 2);
            int c0 = nt * 8 + (lane & 3) * 2;
            stage[r0 * 33 + c0]           = acc[mi][nt][0];
            stage[r0 * 33 + c0 + 1]       = acc[mi][nt][1];
            stage[(r0 + 8) * 33 + c0]     = acc[mi][nt][2];
            stage[(r0 + 8) * 33 + c0 + 1] = acc[mi][nt][3];
        }
    float* zbuf = (float*)(smem + COFFZ);
    zbuf[crow * 8 + cseg] = zacc;
    __syncthreads();

    {
        float* base = (float*)smem;
        int j0 = tid * 4;
        int d = j0 >> 5, e = j0 & 31;
        float4 s = make_float4(0.f, 0.f, 0.f, 0.f);
        #pragma unroll
        for (int ww = 0; ww < 8; ww++) {
            float* p2 = base + ww * 1056 + d * 33 + e;
            s.x += p2[0]; s.y += p2[1]; s.z += p2[2]; s.w += p2[3];
        }
        *(float4*)(ctxp + ((size_t)chunk * 256 + bh) * 1024 + j0) = s;
        if (tid < 32) {
            float zz = 0.f;
            #pragma unroll
            for (int g = 0; g < 8; g++) zz += zbuf[tid * 8 + g];
            zp[((size_t)chunk * 256 + bh) * 32 + tid] = zz;
        }
    }
}

// ---------------------------------------------------------------------------
// fused weight: ctx = (sum_c P_c) / z, Wf[o][h*32+d] = sum_e w_out[o][e]*ctx[d][e]
// ---------------------------------------------------------------------------
__global__ void __launch_bounds__(256) k_wf(const float* __restrict__ w_out,
                                            const float* __restrict__ ctxp,
                                            const float* __restrict__ zp,
                                            __half* __restrict__ wfh,
                                            __half* __restrict__ wfl) {
    int head = blockIdx.x, bi = blockIdx.y;
    int bh = bi * HEADS + head;
    __shared__ float cs[DH][33];
    __shared__ float z_s[DH];
    int tid = threadIdx.x;

    if (tid < 32) {
        float zz = 0.f;
        #pragma unroll
        for (int c = 0; c < CHUNKS; c++) zz += zp[((size_t)c * 256 + bh) * 32 + tid];
        z_s[tid] = zz;
    }
    __syncthreads();
    for (int i = tid; i < DH * DH; i += 256) {
        float s = 0.f;
        #pragma unroll
        for (int c = 0; c < CHUNKS; c++) s += ctxp[((size_t)c * 256 + bh) * 1024 + i];
        cs[i >> 5][i & 31] = s / z_s[i >> 5];
    }
    __syncthreads();

    int d = tid & 31, og = tid >> 5;
    for (int o = og; o < CH; o += 8) {
        const float* wrow = w_out + (size_t)o * CH + head * DH;
        float acc = 0.f;
        #pragma unroll
        for (int e = 0; e < DH; e++) acc += wrow[e] * cs[d][e];
        size_t oidx = (size_t)bi * CH * CH + (size_t)o * CH + head * DH + d;
        __half h = __float2half(acc);
        wfh[oidx] = h;
        wfl[oidx] = __float2half(acc - __half2float(h));
    }
}

// ---------------------------------------------------------------------------
extern "C" void kernel_launch(void* const* d_in, const int* in_sizes, int n_in,
                              void* d_out, int out_size) {
    const float* x     = (const float*)d_in[0];
    const float* w_qkv = (const float*)d_in[1];
    const float* w_out = (const float*)d_in[2];
    const float* b_out = (const float*)d_in[3];
    float* out = (float*)d_out;

    __half *xh, *wh, *wl, *qh, *vh, *vl, *wfh, *wfl;
    float *kf, *ctxp, *zp;
    cudaGetSymbolAddress((void**)&xh,   g_xh);
    cudaGetSymbolAddress((void**)&wh,   g_wh);
    cudaGetSymbolAddress((void**)&wl,   g_wl);
    cudaGetSymbolAddress((void**)&qh,   g_qh);
    cudaGetSymbolAddress((void**)&kf,   g_kf);
    cudaGetSymbolAddress((void**)&vh,   g_vh);
    cudaGetSymbolAddress((void**)&vl,   g_vl);
    cudaGetSymbolAddress((void**)&ctxp, g_ctxp);
    cudaGetSymbolAddress((void**)&zp,   g_zp);
    cudaGetSymbolAddress((void**)&wfh,  g_wfh);
    cudaGetSymbolAddress((void**)&wfl,  g_wfl);

    cudaFuncSetAttribute(k_pgemm<false>, cudaFuncAttributeMaxDynamicSharedMemorySize, GEMM_SMEM);
    cudaFuncSetAttribute(k_pgemm<true>,  cudaFuncAttributeMaxDynamicSharedMemorySize, GEMM_SMEM);
    cudaFuncSetAttribute(k_context_tc,   cudaFuncAttributeMaxDynamicSharedMemorySize, CTX_SMEM);

    // 0. splits
    k_split_x<<<(BATCH * CH * FRAMES * NPIX) / 1024, 256>>>(x, xh);
    k_split_w<<<(QKV_M * CH) / 1024, 256>>>(w_qkv, wh, wl);
    // 1. QKV GEMM; epilogues: q softmax->fp16, k->fp32, v->fp16 hi/lo
    k_pgemm<false><<<dim3(2, QKV_M / 128, BF), 256, GEMM_SMEM>>>(
        wh, wl, xh, nullptr, nullptr, qh, kf, vh, vl);
    // 2. tensor-core context partials
    k_context_tc<<<dim3(HEADS, BF, CHUNKS), 256, CTX_SMEM>>>(kf, vh, vl, ctxp, zp);
    // 3. fused weight (reduce partials, divide by z) -> fp16 hi/lo
    k_wf<<<dim3(HEADS, BF), 256>>>(w_out, ctxp, zp, wfh, wfl);
    // 4. output GEMM + bias + scatter
    k_pgemm<true><<<dim3(4, CH / 128, BF), 256, GEMM_SMEM>>>(
        wfh, wfl, qh, b_out, out, nullptr, nullptr, nullptr, nullptr);
}

// round 10
// speedup vs baseline: 3.6876x; 1.1962x over previous
#include <cuda_runtime.h>
#include <cuda_bf16.h>
#include <cuda_fp16.h>
#include <math_constants.h>
#include <cstdint>

// Problem constants
#define BATCH   2
#define CH      256
#define FRAMES  16
#define NPIX    4096
#define BF      32
#define HEADS   8
#define DH      32
#define QKV_M   768
#define XSTRIDE (FRAMES*NPIX)
#define CHUNKS  4
#define CK_N    1024

// ---------------------------------------------------------------------------
// Scratch
// ---------------------------------------------------------------------------
__device__ __half g_xh[(size_t)BATCH * CH * FRAMES * NPIX];
__device__ __half g_wh[(size_t)QKV_M * CH];
__device__ __half g_wl[(size_t)QKV_M * CH];
__device__ __half g_qh[(size_t)BF * CH * NPIX];    // softmaxed q fp16
__device__ __half g_sh[(size_t)BF * CH * NPIX];    // exp(k) fp16 hi
__device__ __half g_sl[(size_t)BF * CH * NPIX];    // exp(k) fp16 lo
__device__ __half g_vh[(size_t)BF * CH * NPIX];    // v fp16 hi
__device__ __half g_vl[(size_t)BF * CH * NPIX];    // v fp16 lo
__device__ float  g_zp[(size_t)BF * 256 * 32];     // z partials [bi][row][nchunk]
__device__ float  g_ctxp[(size_t)CHUNKS * BF * HEADS * DH * DH];
__device__ __half g_wfh[(size_t)BF * CH * CH];
__device__ __half g_wfl[(size_t)BF * CH * CH];

__device__ __forceinline__ uint32_t smem_u32(const void* p) {
    uint32_t a;
    asm("{ .reg .u64 t; cvta.to.shared.u64 t, %1; cvt.u32.u64 %0, t; }" : "=r"(a) : "l"(p));
    return a;
}
__device__ __forceinline__ void cp16(uint32_t dst, const void* src) {
    asm volatile("cp.async.cg.shared.global [%0], [%1], 16;" :: "r"(dst), "l"(src) : "memory");
}
__device__ __forceinline__ void ldsm4(uint32_t* r, uint32_t addr) {
    asm volatile("ldmatrix.sync.aligned.m8n8.x4.shared.b16 {%0,%1,%2,%3}, [%4];"
                 : "=r"(r[0]), "=r"(r[1]), "=r"(r[2]), "=r"(r[3]) : "r"(addr));
}
__device__ __forceinline__ void ldsm4t(uint32_t* r, uint32_t addr) {
    asm volatile("ldmatrix.sync.aligned.m8n8.x4.trans.shared.b16 {%0,%1,%2,%3}, [%4];"
                 : "=r"(r[0]), "=r"(r[1]), "=r"(r[2]), "=r"(r[3]) : "r"(addr));
}
__device__ __forceinline__ void mma_fp16(float* c, const uint32_t* a, const uint32_t* b) {
    asm volatile("mma.sync.aligned.m16n8k16.row.col.f32.f16.f16.f32 "
                 "{%0,%1,%2,%3}, {%4,%5,%6,%7}, {%8,%9}, {%0,%1,%2,%3};"
                 : "+f"(c[0]), "+f"(c[1]), "+f"(c[2]), "+f"(c[3])
                 : "r"(a[0]), "r"(a[1]), "r"(a[2]), "r"(a[3]), "r"(b[0]), "r"(b[1]));
}
__device__ __forceinline__ void mma_fp16_2(float* c, const uint32_t* a,
                                           uint32_t b0, uint32_t b1) {
    asm volatile("mma.sync.aligned.m16n8k16.row.col.f32.f16.f16.f32 "
                 "{%0,%1,%2,%3}, {%4,%5,%6,%7}, {%8,%9}, {%0,%1,%2,%3};"
                 : "+f"(c[0]), "+f"(c[1]), "+f"(c[2]), "+f"(c[3])
                 : "r"(a[0]), "r"(a[1]), "r"(a[2]), "r"(a[3]), "r"(b0), "r"(b1));
}

// ---------------------------------------------------------------------------
// Splits
// ---------------------------------------------------------------------------
__global__ void k_split_w(const float* __restrict__ src,
                          __half* __restrict__ hi, __half* __restrict__ lo) {
    size_t i = ((size_t)blockIdx.x * 256 + threadIdx.x) * 4;
    float4 v = *(const float4*)(src + i);
    __half h0 = __float2half(v.x), h1 = __float2half(v.y);
    __half h2 = __float2half(v.z), h3 = __float2half(v.w);
    __half l0 = __float2half(v.x - __half2float(h0));
    __half l1 = __float2half(v.y - __half2float(h1));
    __half l2 = __float2half(v.z - __half2float(h2));
    __half l3 = __float2half(v.w - __half2float(h3));
    __half2* hp = (__half2*)(hi + i);
    __half2* lp = (__half2*)(lo + i);
    hp[0] = __half2(h0, h1); hp[1] = __half2(h2, h3);
    lp[0] = __half2(l0, l1); lp[1] = __half2(l2, l3);
}
__global__ void k_split_x(const float* __restrict__ src, __half* __restrict__ dst) {
    size_t i = ((size_t)blockIdx.x * 256 + threadIdx.x) * 4;
    float4 v = *(const float4*)(src + i);
    __half2* dp = (__half2*)(dst + i);
    dp[0] = __half2(__float2half(v.x), __float2half(v.y));
    dp[1] = __half2(__float2half(v.z), __float2half(v.w));
}

// ---------------------------------------------------------------------------
// Streaming 2-product fp16 GEMM, 3-stage pipeline, 2 CTAs/SM.
// One 128x128 output tile per CTA; A(hi/lo) and B streamed per k-step of 32.
// OUT_MODE=false: qkv. TILE_KIND: 0=q (softmax->qh fp16), 1=k (exp->sh/sl +
//                 z partials), 2=v (vh/vl).
// OUT_MODE=true : out = Wf @ qh + bias, scatter.
// ---------------------------------------------------------------------------
#define PA2    80                          // A row pitch (32 fp16 + 16B pad)
#define SZ_A2  (128 * PA2)                 // 10240 per half
#define PB     272                         // B row pitch (128 fp16 + 16B pad)
#define SZ_B2  (32 * PB)                   // 8704
#define OFF_B2 (2 * SZ_A2)                 // 20480
#define STAGE2 (OFF_B2 + SZ_B2)            // 29184
#define SGEMM_SMEM (3 * STAGE2)            // 87552

template <bool OUT_MODE>
__global__ void __launch_bounds__(256, 2) k_sgemm(const __half* __restrict__ Ah_g,
                                                  const __half* __restrict__ Al_g,
                                                  const __half* __restrict__ Bh_g,
                                                  const float* __restrict__ bias,
                                                  float* __restrict__ outp,
                                                  __half* __restrict__ qout,
                                                  __half* __restrict__ shout,
                                                  __half* __restrict__ slout,
                                                  __half* __restrict__ vhout,
                                                  __half* __restrict__ vlout,
                                                  float* __restrict__ zp) {
    extern __shared__ char smem[];
    const uint32_t sb0 = smem_u32(smem);
    int tid = threadIdx.x, w = tid >> 5, lane = tid & 31;
    int m0 = blockIdx.y * 128;
    int n0 = blockIdx.x * 128;
    int bi = blockIdx.z, b = bi >> 4, f = bi & 15;
    const int TILE_KIND = OUT_MODE ? 3 : (int)(blockIdx.y >> 1);

    const __half* Ah = Ah_g + (OUT_MODE ? (size_t)bi * CH * CH : 0);
    const __half* Al = Al_g + (OUT_MODE ? (size_t)bi * CH * CH : 0);
    const size_t bstride = OUT_MODE ? (size_t)NPIX : (size_t)XSTRIDE;
    const __half* Bh = Bh_g + (OUT_MODE ? (size_t)bi * CH * NPIX
                                        : ((size_t)(b * CH) * FRAMES + f) * NPIX);

    auto loadStage = [&](int s, int kt) {
        uint32_t sb = sb0 + (uint32_t)s * STAGE2;
        // A hi/lo: 512 16B-chunks per half
        #pragma unroll
        for (int i = 0; i < 2; i++) {
            int ch = tid + i * 256;
            int r = ch >> 2, c = ch & 3;
            size_t goff = (size_t)(m0 + r) * CH + kt * 32 + c * 8;
            uint32_t d = sb + r * PA2 + c * 16;
            cp16(d, Ah + goff);
            cp16(d + SZ_A2, Al + goff);
        }
        // B: 512 chunks
        #pragma unroll
        for (int i = 0; i < 2; i++) {
            int ch = tid + i * 256;
            int r = ch >> 4, c = ch & 15;
            cp16(sb + OFF_B2 + r * PB + c * 16,
                 Bh + (size_t)(kt * 32 + r) * bstride + n0 + c * 8);
        }
        asm volatile("cp.async.commit_group;" ::: "memory");
    };

    int wm = (w & 1) * 64;
    int wn = (w >> 1) * 32;
    uint32_t aRel = (uint32_t)(wm + (lane & 15)) * PA2 + (uint32_t)(lane >> 4) * 16;
    uint32_t bRel = OFF_B2 + (uint32_t)(lane & 15) * PB + (uint32_t)(lane >> 4) * 16
                  + (uint32_t)wn * 2;

    float acc[4][4][4];
    #pragma unroll
    for (int i = 0; i < 4; i++)
        #pragma unroll
        for (int j = 0; j < 4; j++)
            #pragma unroll
            for (int r = 0; r < 4; r++) acc[i][j][r] = 0.f;

    loadStage(0, 0);
    loadStage(1, 1);

    #pragma unroll
    for (int kt = 0; kt < 8; kt++) {
        asm volatile("cp.async.wait_group 1;" ::: "memory");
        __syncthreads();
        if (kt < 6) loadStage((kt + 2) % 3, kt + 2);
        else asm volatile("cp.async.commit_group;" ::: "memory");

        uint32_t sb = sb0 + (uint32_t)(kt % 3) * STAGE2;
        #pragma unroll
        for (int ks = 0; ks < 2; ks++) {
            uint32_t aHf[4][4], aLf[4][4], bHf[2][4];
            #pragma unroll
            for (int mi = 0; mi < 4; mi++) {
                uint32_t ad = sb + aRel + (uint32_t)(mi * 16) * PA2 + ks * 32;
                ldsm4(aHf[mi], ad);
                ldsm4(aLf[mi], ad + SZ_A2);
            }
            #pragma unroll
            for (int ng = 0; ng < 2; ng++) {
                uint32_t bd = sb + bRel + (uint32_t)(ks * 16) * PB + ng * 32;
                ldsm4t(bHf[ng], bd);
            }
            #pragma unroll
            for (int mi = 0; mi < 4; mi++)
                #pragma unroll
                for (int ni = 0; ni < 4; ni++) {
                    const uint32_t* bh = &bHf[ni >> 1][(ni & 1) * 2];
                    mma_fp16(acc[mi][ni], aHf[mi], bh);
                    mma_fp16(acc[mi][ni], aLf[mi], bh);
                }
        }
    }

    // ---------------- epilogues ----------------
    if (TILE_KIND == 0) {
        // q: fused softmax over d (head = 2 consecutive mi), store fp16
        #pragma unroll
        for (int h = 0; h < 2; h++) {
            int mi0 = 2 * h, mi1 = 2 * h + 1;
            #pragma unroll
            for (int ni = 0; ni < 4; ni++) {
                #pragma unroll
                for (int p = 0; p < 2; p++) {
                    float v0 = acc[mi0][ni][p],     v1 = acc[mi0][ni][p + 2];
                    float v2 = acc[mi1][ni][p],     v3 = acc[mi1][ni][p + 2];
                    float mx = fmaxf(fmaxf(v0, v1), fmaxf(v2, v3));
                    mx = fmaxf(mx, __shfl_xor_sync(0xffffffffu, mx, 4));
                    mx = fmaxf(mx, __shfl_xor_sync(0xffffffffu, mx, 8));
                    mx = fmaxf(mx, __shfl_xor_sync(0xffffffffu, mx, 16));
                    v0 = __expf(v0 - mx); v1 = __expf(v1 - mx);
                    v2 = __expf(v2 - mx); v3 = __expf(v3 - mx);
                    float s = v0 + v1 + v2 + v3;
                    s += __shfl_xor_sync(0xffffffffu, s, 4);
                    s += __shfl_xor_sync(0xffffffffu, s, 8);
                    s += __shfl_xor_sync(0xffffffffu, s, 16);
                    float inv = 0.17677669529663687f / s;
                    acc[mi0][ni][p]     = v0 * inv;
                    acc[mi0][ni][p + 2] = v1 * inv;
                    acc[mi1][ni][p]     = v2 * inv;
                    acc[mi1][ni][p + 2] = v3 * inv;
                }
            }
        }
        __half* qbase = qout + (size_t)bi * CH * NPIX;
        #pragma unroll
        for (int mi = 0; mi < 4; mi++)
            #pragma unroll
            for (int ni = 0; ni < 4; ni++) {
                int r0 = m0 + wm + mi * 16 + (lane >> 2);
                int cc = n0 + wn + ni * 8 + (lane & 3) * 2;
                *(__half2*)(qbase + (size_t)r0 * NPIX + cc) =
                    __half2(__float2half(acc[mi][ni][0]), __float2half(acc[mi][ni][1]));
                *(__half2*)(qbase + (size_t)(r0 + 8) * NPIX + cc) =
                    __half2(__float2half(acc[mi][ni][2]), __float2half(acc[mi][ni][3]));
            }
    } else if (TILE_KIND == 1) {
        // k: exp -> fp16 hi/lo + z partials
        __half* shb = shout + (size_t)bi * CH * NPIX;
        __half* slb = slout + (size_t)bi * CH * NPIX;
        float zloc[4][2];
        #pragma unroll
        for (int mi = 0; mi < 4; mi++) { zloc[mi][0] = 0.f; zloc[mi][1] = 0.f; }
        #pragma unroll
        for (int mi = 0; mi < 4; mi++)
            #pragma unroll
            for (int ni = 0; ni < 4; ni++) {
                int r0 = m0 - 256 + wm + mi * 16 + (lane >> 2);
                int cc = n0 + wn + ni * 8 + (lane & 3) * 2;
                #pragma unroll
                for (int rr = 0; rr < 2; rr++) {
                    float e0 = __expf(acc[mi][ni][rr * 2]);
                    float e1 = __expf(acc[mi][ni][rr * 2 + 1]);
                    zloc[mi][rr] += e0 + e1;
                    __half h0 = __float2half(e0), h1 = __float2half(e1);
                    __half l0 = __float2half(e0 - __half2float(h0));
                    __half l1 = __float2half(e1 - __half2float(h1));
                    size_t off = (size_t)(r0 + rr * 8) * NPIX + cc;
                    *(__half2*)(shb + off) = __half2(h0, h1);
                    *(__half2*)(slb + off) = __half2(l0, l1);
                }
            }
        // reduce z across the 4 column-lanes, stage per warp-column, reduce, store
        #pragma unroll
        for (int mi = 0; mi < 4; mi++)
            #pragma unroll
            for (int rr = 0; rr < 2; rr++) {
                zloc[mi][rr] += __shfl_xor_sync(0xffffffffu, zloc[mi][rr], 1);
                zloc[mi][rr] += __shfl_xor_sync(0xffffffffu, zloc[mi][rr], 2);
            }
        __syncthreads();                       // stage smem now safe to reuse
        float* zs = (float*)smem;              // [128][4]
        if ((lane & 3) == 0) {
            #pragma unroll
            for (int mi = 0; mi < 4; mi++)
                #pragma unroll
                for (int rr = 0; rr < 2; rr++) {
                    int row = wm + mi * 16 + (lane >> 2) + rr * 8;
                    zs[row * 4 + (w >> 1)] = zloc[mi][rr];
                }
        }
        __syncthreads();
        if (tid < 128) {
            float z = zs[tid * 4] + zs[tid * 4 + 1] + zs[tid * 4 + 2] + zs[tid * 4 + 3];
            zp[((size_t)bi * 256 + (m0 - 256) + tid) * 32 + blockIdx.x] = z;
        }
    } else if (TILE_KIND == 2) {
        // v: fp16 hi/lo
        __half* vhb = vhout + (size_t)bi * CH * NPIX;
        __half* vlb = vlout + (size_t)bi * CH * NPIX;
        #pragma unroll
        for (int mi = 0; mi < 4; mi++)
            #pragma unroll
            for (int ni = 0; ni < 4; ni++) {
                int r0 = m0 - 512 + wm + mi * 16 + (lane >> 2);
                int cc = n0 + wn + ni * 8 + (lane & 3) * 2;
                #pragma unroll
                for (int rr = 0; rr < 2; rr++) {
                    float a0 = acc[mi][ni][rr * 2], a1 = acc[mi][ni][rr * 2 + 1];
                    __half h0 = __float2half(a0), h1 = __float2half(a1);
                    __half l0 = __float2half(a0 - __half2float(h0));
                    __half l1 = __float2half(a1 - __half2float(h1));
                    size_t off = (size_t)(r0 + rr * 8) * NPIX + cc;
                    *(__half2*)(vhb + off) = __half2(h0, h1);
                    *(__half2*)(vlb + off) = __half2(l0, l1);
                }
            }
    } else {
        // out: + bias, scatter
        #pragma unroll
        for (int mi = 0; mi < 4; mi++)
            #pragma unroll
            for (int ni = 0; ni < 4; ni++) {
                int r0 = m0 + wm + mi * 16 + (lane >> 2);
                int r1 = r0 + 8;
                int cc = n0 + wn + ni * 8 + (lane & 3) * 2;
                float b0 = bias[r0], b1 = bias[r1];
                float* p0 = outp + ((size_t)(b * CH + r0) * FRAMES + f) * NPIX + cc;
                float* p1 = outp + ((size_t)(b * CH + r1) * FRAMES + f) * NPIX + cc;
                *(float2*)p0 = make_float2(acc[mi][ni][0] + b0, acc[mi][ni][1] + b0);
                *(float2*)p1 = make_float2(acc[mi][ni][2] + b1, acc[mi][ni][3] + b1);
            }
    }
}

// ---------------------------------------------------------------------------
// Tensor-core context: P[d][e] = sum_n S[d,n]*v[e,n], S = exp(k) (hi/lo fp16).
// Grid (HEADS, BF, CHUNKS); 3-stage cp.async, 3-product mma, partials to gmem.
// ---------------------------------------------------------------------------
#define C2P    272
#define C2SZ   (32 * C2P)                // 8704
#define C2STG  (4 * C2SZ)                // 34816
#define CTX2_SMEM (3 * C2STG)            // 104448

__global__ void __launch_bounds__(256, 2) k_context_tc(const __half* __restrict__ sh,
                                                       const __half* __restrict__ sl,
                                                       const __half* __restrict__ vh,
                                                       const __half* __restrict__ vl,
                                                       float* __restrict__ ctxp) {
    extern __shared__ char smem[];
    const uint32_t sb0 = smem_u32(smem);
    int tid = threadIdx.x, w = tid >> 5, lane = tid & 31;
    int head = blockIdx.x, bi = blockIdx.y, chunk = blockIdx.z;
    int bh = bi * HEADS + head;

    size_t base = ((size_t)bi * CH + head * DH) * NPIX + chunk * CK_N;
    const __half* s_h = sh + base;
    const __half* s_l = sl + base;
    const __half* v_h = vh + base;
    const __half* v_l = vl + base;

    auto loadT = [&](int s, int p) {
        int n0 = p * 128;
        uint32_t sb = sb0 + (uint32_t)s * C2STG;
        #pragma unroll
        for (int i = 0; i < 2; i++) {
            int ch = tid + i * 256;
            int r = ch >> 4, c = ch & 15;
            size_t go = (size_t)r * NPIX + n0 + c * 8;
            uint32_t d = sb + r * C2P + c * 16;
            cp16(d, s_h + go);
            cp16(d + C2SZ, s_l + go);
            cp16(d + 2 * C2SZ, v_h + go);
            cp16(d + 3 * C2SZ, v_l + go);
        }
        asm volatile("cp.async.commit_group;" ::: "memory");
    };

    float acc[2][4][4];
    #pragma unroll
    for (int i = 0; i < 2; i++)
        #pragma unroll
        for (int j = 0; j < 4; j++)
            #pragma unroll
            for (int r = 0; r < 4; r++) acc[i][j][r] = 0.f;

    loadT(0, 0);
    loadT(1, 1);

    uint32_t cb = (uint32_t)w * 32 + (uint32_t)(lane >> 4) * 16;

    #pragma unroll
    for (int p = 0; p < 8; p++) {
        asm volatile("cp.async.wait_group 1;" ::: "memory");
        __syncthreads();
        if (p < 6) loadT((p + 2) % 3, p + 2);
        else asm volatile("cp.async.commit_group;" ::: "memory");

        uint32_t sb = sb0 + (uint32_t)(p % 3) * C2STG;
        uint32_t shf[2][4], slf[2][4];
        #pragma unroll
        for (int mi = 0; mi < 2; mi++) {
            uint32_t sa = sb + (uint32_t)(mi * 16 + (lane & 15)) * C2P + cb;
            ldsm4(shf[mi], sa);
            ldsm4(slf[mi], sa + C2SZ);
        }
        #pragma unroll
        for (int ei = 0; ei < 2; ei++) {
            uint32_t vhf[4], vlf[4];
            uint32_t va = sb + 2 * C2SZ + (uint32_t)(ei * 16 + (lane & 15)) * C2P + cb;
            ldsm4(vhf, va);
            ldsm4(vlf, va + C2SZ);
            #pragma unroll
            for (int pick = 0; pick < 2; pick++) {
                int nt = ei * 2 + pick;
                #pragma unroll
                for (int mi = 0; mi < 2; mi++) {
                    mma_fp16_2(acc[mi][nt], shf[mi], vhf[pick], vhf[pick + 2]);
                    mma_fp16_2(acc[mi][nt], slf[mi], vhf[pick], vhf[pick + 2]);
                    mma_fp16_2(acc[mi][nt], shf[mi], vlf[pick], vlf[pick + 2]);
                }
            }
        }
    }

    // reduce across 8 warps via smem (overlays stages)
    __syncthreads();
    float* stage = (float*)smem + w * 1056;    // 32 x 33 per warp
    #pragma unroll
    for (int mi = 0; mi < 2; mi++)
        #pragma unroll
        for (int nt = 0; nt < 4; nt++) {
            int r0 = mi * 16 + (lane >> 2);
            int c0 = nt * 8 + (lane & 3) * 2;
            stage[r0 * 33 + c0]           = acc[mi][nt][0];
            stage[r0 * 33 + c0 + 1]       = acc[mi][nt][1];
            stage[(r0 + 8) * 33 + c0]     = acc[mi][nt][2];
            stage[(r0 + 8) * 33 + c0 + 1] = acc[mi][nt][3];
        }
    __syncthreads();
    {
        float* basep = (float*)smem;
        int j0 = tid * 4;
        int d = j0 >> 5, e = j0 & 31;
        float4 s = make_float4(0.f, 0.f, 0.f, 0.f);
        #pragma unroll
        for (int ww = 0; ww < 8; ww++) {
            float* p2 = basep + ww * 1056 + d * 33 + e;
            s.x += p2[0]; s.y += p2[1]; s.z += p2[2]; s.w += p2[3];
        }
        *(float4*)(ctxp + ((size_t)chunk * 256 + bh) * 1024 + j0) = s;
    }
}

// ---------------------------------------------------------------------------
// fused weight: ctx = (sum_c P_c) / z, Wf = w_out(head slice) @ ctx^T -> fp16 hi/lo
// ---------------------------------------------------------------------------
__global__ void __launch_bounds__(256) k_wf(const float* __restrict__ w_out,
                                            const float* __restrict__ ctxp,
                                            const float* __restrict__ zp,
                                            __half* __restrict__ wfh,
                                            __half* __restrict__ wfl) {
    int head = blockIdx.x, bi = blockIdx.y;
    int bh = bi * HEADS + head;
    __shared__ float cs[DH][33];
    __shared__ float z_s[DH];
    int tid = threadIdx.x;

    if (tid < 32) {
        const float* zrow = zp + ((size_t)bi * 256 + head * DH + tid) * 32;
        float zz = 0.f;
        #pragma unroll
        for (int c = 0; c < 32; c++) zz += zrow[c];
        z_s[tid] = zz;
    }
    __syncthreads();
    for (int i = tid; i < DH * DH; i += 256) {
        float s = 0.f;
        #pragma unroll
        for (int c = 0; c < CHUNKS; c++) s += ctxp[((size_t)c * 256 + bh) * 1024 + i];
        cs[i >> 5][i & 31] = s / z_s[i >> 5];
    }
    __syncthreads();

    int d = tid & 31, og = tid >> 5;
    for (int o = og; o < CH; o += 8) {
        const float* wrow = w_out + (size_t)o * CH + head * DH;
        float acc = 0.f;
        #pragma unroll
        for (int e = 0; e < DH; e++) acc += wrow[e] * cs[d][e];
        size_t oidx = (size_t)bi * CH * CH + (size_t)o * CH + head * DH + d;
        __half h = __float2half(acc);
        wfh[oidx] = h;
        wfl[oidx] = __float2half(acc - __half2float(h));
    }
}

// ---------------------------------------------------------------------------
extern "C" void kernel_launch(void* const* d_in, const int* in_sizes, int n_in,
                              void* d_out, int out_size) {
    const float* x     = (const float*)d_in[0];
    const float* w_qkv = (const float*)d_in[1];
    const float* w_out = (const float*)d_in[2];
    const float* b_out = (const float*)d_in[3];
    float* out = (float*)d_out;

    __half *xh, *wh, *wl, *qh, *sh, *sl, *vh, *vl, *wfh, *wfl;
    float *ctxp, *zp;
    cudaGetSymbolAddress((void**)&xh,   g_xh);
    cudaGetSymbolAddress((void**)&wh,   g_wh);
    cudaGetSymbolAddress((void**)&wl,   g_wl);
    cudaGetSymbolAddress((void**)&qh,   g_qh);
    cudaGetSymbolAddress((void**)&sh,   g_sh);
    cudaGetSymbolAddress((void**)&sl,   g_sl);
    cudaGetSymbolAddress((void**)&vh,   g_vh);
    cudaGetSymbolAddress((void**)&vl,   g_vl);
    cudaGetSymbolAddress((void**)&ctxp, g_ctxp);
    cudaGetSymbolAddress((void**)&zp,   g_zp);
    cudaGetSymbolAddress((void**)&wfh,  g_wfh);
    cudaGetSymbolAddress((void**)&wfl,  g_wfl);

    cudaFuncSetAttribute(k_sgemm<false>, cudaFuncAttributeMaxDynamicSharedMemorySize, SGEMM_SMEM);
    cudaFuncSetAttribute(k_sgemm<true>,  cudaFuncAttributeMaxDynamicSharedMemorySize, SGEMM_SMEM);
    cudaFuncSetAttribute(k_context_tc,   cudaFuncAttributeMaxDynamicSharedMemorySize, CTX2_SMEM);

    // 0. splits
    k_split_x<<<(BATCH * CH * FRAMES * NPIX) / 1024, 256>>>(x, xh);
    k_split_w<<<(QKV_M * CH) / 1024, 256>>>(w_qkv, wh, wl);
    // 1. QKV GEMM; epilogues: q softmax->fp16, k->exp hi/lo + z, v->hi/lo
    k_sgemm<false><<<dim3(NPIX / 128, QKV_M / 128, BF), 256, SGEMM_SMEM>>>(
        wh, wl, xh, nullptr, nullptr, qh, sh, sl, vh, vl, zp);
    // 2. tensor-core context partials
    k_context_tc<<<dim3(HEADS, BF, CHUNKS), 256, CTX2_SMEM>>>(sh, sl, vh, vl, ctxp);
    // 3. fused weight (reduce partials, divide by z) -> fp16 hi/lo
    k_wf<<<dim3(HEADS, BF), 256>>>(w_out, ctxp, zp, wfh, wfl);
    // 4. output GEMM + bias + scatter
    k_sgemm<true><<<dim3(NPIX / 128, CH / 128, BF), 256, SGEMM_SMEM>>>(
        wfh, wfl, qh, b_out, out, nullptr, nullptr, nullptr, nullptr, nullptr, nullptr);
}

// round 11
// speedup vs baseline: 4.8107x; 1.3046x over previous
#include <cuda_runtime.h>
#include <cuda_bf16.h>
#include <cuda_fp16.h>
#include <math_constants.h>
#include <cstdint>

// Problem constants
#define BATCH   2
#define CH      256
#define FRAMES  16
#define NPIX    4096
#define BF      32
#define HEADS   8
#define DH      32
#define QKV_M   768
#define XSTRIDE (FRAMES*NPIX)
#define CHUNKS  4
#define CK_N    1024

// ---------------------------------------------------------------------------
// Scratch
// ---------------------------------------------------------------------------
__device__ __half g_xh[(size_t)BATCH * CH * FRAMES * NPIX];
__device__ __half g_wh[(size_t)QKV_M * CH];        // W single fp16
__device__ __half g_qh[(size_t)BF * CH * NPIX];    // softmaxed q fp16
__device__ __half g_sh[(size_t)BF * CH * NPIX];    // exp(k) fp16 hi
__device__ __half g_sl[(size_t)BF * CH * NPIX];    // exp(k) fp16 lo
__device__ __half g_vh[(size_t)BF * CH * NPIX];    // v fp16 (single)
__device__ float  g_zp[(size_t)BF * 256 * 32];     // z partials [bi][row][nchunk]
__device__ float  g_ctxp[(size_t)CHUNKS * BF * HEADS * DH * DH];
__device__ __half g_wfh[(size_t)BF * CH * CH];
__device__ __half g_wfl[(size_t)BF * CH * CH];

__device__ __forceinline__ uint32_t smem_u32(const void* p) {
    uint32_t a;
    asm("{ .reg .u64 t; cvta.to.shared.u64 t, %1; cvt.u32.u64 %0, t; }" : "=r"(a) : "l"(p));
    return a;
}
__device__ __forceinline__ void cp16(uint32_t dst, const void* src) {
    asm volatile("cp.async.cg.shared.global [%0], [%1], 16;" :: "r"(dst), "l"(src) : "memory");
}
__device__ __forceinline__ void ldsm4(uint32_t* r, uint32_t addr) {
    asm volatile("ldmatrix.sync.aligned.m8n8.x4.shared.b16 {%0,%1,%2,%3}, [%4];"
                 : "=r"(r[0]), "=r"(r[1]), "=r"(r[2]), "=r"(r[3]) : "r"(addr));
}
__device__ __forceinline__ void ldsm4t(uint32_t* r, uint32_t addr) {
    asm volatile("ldmatrix.sync.aligned.m8n8.x4.trans.shared.b16 {%0,%1,%2,%3}, [%4];"
                 : "=r"(r[0]), "=r"(r[1]), "=r"(r[2]), "=r"(r[3]) : "r"(addr));
}
__device__ __forceinline__ void mma_fp16(float* c, const uint32_t* a, const uint32_t* b) {
    asm volatile("mma.sync.aligned.m16n8k16.row.col.f32.f16.f16.f32 "
                 "{%0,%1,%2,%3}, {%4,%5,%6,%7}, {%8,%9}, {%0,%1,%2,%3};"
                 : "+f"(c[0]), "+f"(c[1]), "+f"(c[2]), "+f"(c[3])
                 : "r"(a[0]), "r"(a[1]), "r"(a[2]), "r"(a[3]), "r"(b[0]), "r"(b[1]));
}
__device__ __forceinline__ void mma_fp16_2(float* c, const uint32_t* a,
                                           uint32_t b0, uint32_t b1) {
    asm volatile("mma.sync.aligned.m16n8k16.row.col.f32.f16.f16.f32 "
                 "{%0,%1,%2,%3}, {%4,%5,%6,%7}, {%8,%9}, {%0,%1,%2,%3};"
                 : "+f"(c[0]), "+f"(c[1]), "+f"(c[2]), "+f"(c[3])
                 : "r"(a[0]), "r"(a[1]), "r"(a[2]), "r"(a[3]), "r"(b0), "r"(b1));
}

// ---------------------------------------------------------------------------
// Splits
// ---------------------------------------------------------------------------
__global__ void k_split1(const float* __restrict__ src, __half* __restrict__ dst) {
    size_t i = ((size_t)blockIdx.x * 256 + threadIdx.x) * 4;
    float4 v = *(const float4*)(src + i);
    __half2* dp = (__half2*)(dst + i);
    dp[0] = __half2(__float2half(v.x), __float2half(v.y));
    dp[1] = __half2(__float2half(v.z), __float2half(v.w));
}

// ---------------------------------------------------------------------------
// Streaming fp16 GEMM, 3-stage pipeline, 2 CTAs/SM.
// OUT_MODE=false: 1-product (A = W single fp16). TILE_KIND by m-block:
//                 0=q (softmax->qh), 1=k (exp->sh/sl + z), 2=v (vh single).
// OUT_MODE=true : 2-product (A = Wf hi/lo). out = Wf @ qh + bias, scatter.
// ---------------------------------------------------------------------------
#define PA2    80                          // A row pitch (32 fp16 + 16B pad)
#define SZ_A2  (128 * PA2)                 // 10240 per half
#define PB     272                         // B row pitch (128 fp16 + 16B pad)
#define SZ_B2  (32 * PB)                   // 8704

template <bool OUT_MODE>
__global__ void __launch_bounds__(256, 2) k_sgemm(const __half* __restrict__ Ah_g,
                                                  const __half* __restrict__ Al_g,
                                                  const __half* __restrict__ Bh_g,
                                                  const float* __restrict__ bias,
                                                  float* __restrict__ outp,
                                                  __half* __restrict__ qout,
                                                  __half* __restrict__ shout,
                                                  __half* __restrict__ slout,
                                                  __half* __restrict__ vhout,
                                                  float* __restrict__ zp) {
    constexpr int NPROD = OUT_MODE ? 2 : 1;
    constexpr uint32_t OFFB2 = NPROD * SZ_A2;
    constexpr uint32_t STG = OFFB2 + SZ_B2;
    extern __shared__ char smem[];
    const uint32_t sb0 = smem_u32(smem);
    int tid = threadIdx.x, w = tid >> 5, lane = tid & 31;
    int m0 = blockIdx.y * 128;
    int n0 = blockIdx.x * 128;
    int bi = blockIdx.z, b = bi >> 4, f = bi & 15;
    const int TILE_KIND = OUT_MODE ? 3 : (int)(blockIdx.y >> 1);

    const __half* Ah = Ah_g + (OUT_MODE ? (size_t)bi * CH * CH : 0);
    const __half* Al = OUT_MODE ? Al_g + (size_t)bi * CH * CH : nullptr;
    const size_t bstride = OUT_MODE ? (size_t)NPIX : (size_t)XSTRIDE;
    const __half* Bh = Bh_g + (OUT_MODE ? (size_t)bi * CH * NPIX
                                        : ((size_t)(b * CH) * FRAMES + f) * NPIX);

    auto loadStage = [&](int s, int kt) {
        uint32_t sb = sb0 + (uint32_t)s * STG;
        #pragma unroll
        for (int i = 0; i < 2; i++) {
            int ch = tid + i * 256;
            int r = ch >> 2, c = ch & 3;
            size_t goff = (size_t)(m0 + r) * CH + kt * 32 + c * 8;
            uint32_t d = sb + r * PA2 + c * 16;
            cp16(d, Ah + goff);
            if (OUT_MODE) cp16(d + SZ_A2, Al + goff);
        }
        #pragma unroll
        for (int i = 0; i < 2; i++) {
            int ch = tid + i * 256;
            int r = ch >> 4, c = ch & 15;
            cp16(sb + OFFB2 + r * PB + c * 16,
                 Bh + (size_t)(kt * 32 + r) * bstride + n0 + c * 8);
        }
        asm volatile("cp.async.commit_group;" ::: "memory");
    };

    int wm = (w & 1) * 64;
    int wn = (w >> 1) * 32;
    uint32_t aRel = (uint32_t)(wm + (lane & 15)) * PA2 + (uint32_t)(lane >> 4) * 16;
    uint32_t bRel = OFFB2 + (uint32_t)(lane & 15) * PB + (uint32_t)(lane >> 4) * 16
                  + (uint32_t)wn * 2;

    float acc[4][4][4];
    #pragma unroll
    for (int i = 0; i < 4; i++)
        #pragma unroll
        for (int j = 0; j < 4; j++)
            #pragma unroll
            for (int r = 0; r < 4; r++) acc[i][j][r] = 0.f;

    loadStage(0, 0);
    loadStage(1, 1);

    #pragma unroll
    for (int kt = 0; kt < 8; kt++) {
        asm volatile("cp.async.wait_group 1;" ::: "memory");
        __syncthreads();
        if (kt < 6) loadStage((kt + 2) % 3, kt + 2);
        else asm volatile("cp.async.commit_group;" ::: "memory");

        uint32_t sb = sb0 + (uint32_t)(kt % 3) * STG;
        #pragma unroll
        for (int ks = 0; ks < 2; ks++) {
            uint32_t aHf[4][4], aLf[4][4], bHf[2][4];
            #pragma unroll
            for (int mi = 0; mi < 4; mi++) {
                uint32_t ad = sb + aRel + (uint32_t)(mi * 16) * PA2 + ks * 32;
                ldsm4(aHf[mi], ad);
                if (OUT_MODE) ldsm4(aLf[mi], ad + SZ_A2);
            }
            #pragma unroll
            for (int ng = 0; ng < 2; ng++) {
                uint32_t bd = sb + bRel + (uint32_t)(ks * 16) * PB + ng * 32;
                ldsm4t(bHf[ng], bd);
            }
            #pragma unroll
            for (int mi = 0; mi < 4; mi++)
                #pragma unroll
                for (int ni = 0; ni < 4; ni++) {
                    const uint32_t* bh = &bHf[ni >> 1][(ni & 1) * 2];
                    mma_fp16(acc[mi][ni], aHf[mi], bh);
                    if (OUT_MODE) mma_fp16(acc[mi][ni], aLf[mi], bh);
                }
        }
    }

    // ---------------- epilogues ----------------
    if (TILE_KIND == 0) {
        // q: fused softmax over d (head = 2 consecutive mi), store fp16
        #pragma unroll
        for (int h = 0; h < 2; h++) {
            int mi0 = 2 * h, mi1 = 2 * h + 1;
            #pragma unroll
            for (int ni = 0; ni < 4; ni++) {
                #pragma unroll
                for (int p = 0; p < 2; p++) {
                    float v0 = acc[mi0][ni][p],     v1 = acc[mi0][ni][p + 2];
                    float v2 = acc[mi1][ni][p],     v3 = acc[mi1][ni][p + 2];
                    float mx = fmaxf(fmaxf(v0, v1), fmaxf(v2, v3));
                    mx = fmaxf(mx, __shfl_xor_sync(0xffffffffu, mx, 4));
                    mx = fmaxf(mx, __shfl_xor_sync(0xffffffffu, mx, 8));
                    mx = fmaxf(mx, __shfl_xor_sync(0xffffffffu, mx, 16));
                    v0 = __expf(v0 - mx); v1 = __expf(v1 - mx);
                    v2 = __expf(v2 - mx); v3 = __expf(v3 - mx);
                    float s = v0 + v1 + v2 + v3;
                    s += __shfl_xor_sync(0xffffffffu, s, 4);
                    s += __shfl_xor_sync(0xffffffffu, s, 8);
                    s += __shfl_xor_sync(0xffffffffu, s, 16);
                    float inv = 0.17677669529663687f / s;
                    acc[mi0][ni][p]     = v0 * inv;
                    acc[mi0][ni][p + 2] = v1 * inv;
                    acc[mi1][ni][p]     = v2 * inv;
                    acc[mi1][ni][p + 2] = v3 * inv;
                }
            }
        }
        __half* qbase = qout + (size_t)bi * CH * NPIX;
        #pragma unroll
        for (int mi = 0; mi < 4; mi++)
            #pragma unroll
            for (int ni = 0; ni < 4; ni++) {
                int r0 = m0 + wm + mi * 16 + (lane >> 2);
                int cc = n0 + wn + ni * 8 + (lane & 3) * 2;
                *(__half2*)(qbase + (size_t)r0 * NPIX + cc) =
                    __half2(__float2half(acc[mi][ni][0]), __float2half(acc[mi][ni][1]));
                *(__half2*)(qbase + (size_t)(r0 + 8) * NPIX + cc) =
                    __half2(__float2half(acc[mi][ni][2]), __float2half(acc[mi][ni][3]));
            }
    } else if (TILE_KIND == 1) {
        // k: exp -> fp16 hi/lo + z partials
        __half* shb = shout + (size_t)bi * CH * NPIX;
        __half* slb = slout + (size_t)bi * CH * NPIX;
        float zloc[4][2];
        #pragma unroll
        for (int mi = 0; mi < 4; mi++) { zloc[mi][0] = 0.f; zloc[mi][1] = 0.f; }
        #pragma unroll
        for (int mi = 0; mi < 4; mi++)
            #pragma unroll
            for (int ni = 0; ni < 4; ni++) {
                int r0 = m0 - 256 + wm + mi * 16 + (lane >> 2);
                int cc = n0 + wn + ni * 8 + (lane & 3) * 2;
                #pragma unroll
                for (int rr = 0; rr < 2; rr++) {
                    float e0 = __expf(acc[mi][ni][rr * 2]);
                    float e1 = __expf(acc[mi][ni][rr * 2 + 1]);
                    zloc[mi][rr] += e0 + e1;
                    __half h0 = __float2half(e0), h1 = __float2half(e1);
                    __half l0 = __float2half(e0 - __half2float(h0));
                    __half l1 = __float2half(e1 - __half2float(h1));
                    size_t off = (size_t)(r0 + rr * 8) * NPIX + cc;
                    *(__half2*)(shb + off) = __half2(h0, h1);
                    *(__half2*)(slb + off) = __half2(l0, l1);
                }
            }
        #pragma unroll
        for (int mi = 0; mi < 4; mi++)
            #pragma unroll
            for (int rr = 0; rr < 2; rr++) {
                zloc[mi][rr] += __shfl_xor_sync(0xffffffffu, zloc[mi][rr], 1);
                zloc[mi][rr] += __shfl_xor_sync(0xffffffffu, zloc[mi][rr], 2);
            }
        __syncthreads();
        float* zs = (float*)smem;              // [128][4]
        if ((lane & 3) == 0) {
            #pragma unroll
            for (int mi = 0; mi < 4; mi++)
                #pragma unroll
                for (int rr = 0; rr < 2; rr++) {
                    int row = wm + mi * 16 + (lane >> 2) + rr * 8;
                    zs[row * 4 + (w >> 1)] = zloc[mi][rr];
                }
        }
        __syncthreads();
        if (tid < 128) {
            float z = zs[tid * 4] + zs[tid * 4 + 1] + zs[tid * 4 + 2] + zs[tid * 4 + 3];
            zp[((size_t)bi * 256 + (m0 - 256) + tid) * 32 + blockIdx.x] = z;
        }
    } else if (TILE_KIND == 2) {
        // v: single fp16
        __half* vhb = vhout + (size_t)bi * CH * NPIX;
        #pragma unroll
        for (int mi = 0; mi < 4; mi++)
            #pragma unroll
            for (int ni = 0; ni < 4; ni++) {
                int r0 = m0 - 512 + wm + mi * 16 + (lane >> 2);
                int cc = n0 + wn + ni * 8 + (lane & 3) * 2;
                #pragma unroll
                for (int rr = 0; rr < 2; rr++) {
                    size_t off = (size_t)(r0 + rr * 8) * NPIX + cc;
                    *(__half2*)(vhb + off) =
                        __half2(__float2half(acc[mi][ni][rr * 2]),
                                __float2half(acc[mi][ni][rr * 2 + 1]));
                }
            }
    } else {
        // out: + bias, scatter
        #pragma unroll
        for (int mi = 0; mi < 4; mi++)
            #pragma unroll
            for (int ni = 0; ni < 4; ni++) {
                int r0 = m0 + wm + mi * 16 + (lane >> 2);
                int r1 = r0 + 8;
                int cc = n0 + wn + ni * 8 + (lane & 3) * 2;
                float b0 = bias[r0], b1 = bias[r1];
                float* p0 = outp + ((size_t)(b * CH + r0) * FRAMES + f) * NPIX + cc;
                float* p1 = outp + ((size_t)(b * CH + r1) * FRAMES + f) * NPIX + cc;
                *(float2*)p0 = make_float2(acc[mi][ni][0] + b0, acc[mi][ni][1] + b0);
                *(float2*)p1 = make_float2(acc[mi][ni][2] + b1, acc[mi][ni][3] + b1);
            }
    }
}

#define SGEMM_SMEM_QKV (3 * (SZ_A2 + SZ_B2))        // 56832
#define SGEMM_SMEM_OUT (3 * (2 * SZ_A2 + SZ_B2))    // 87552

// ---------------------------------------------------------------------------
// Tensor-core context: P[d][e] = sum_n S[d,n]*v[e,n], S = exp(k) hi/lo, v single.
// Grid (HEADS, BF, CHUNKS); 3-stage cp.async, 2-product mma, partials to gmem.
// ---------------------------------------------------------------------------
#define C2P    272
#define C2SZ   (32 * C2P)                // 8704
#define C2STG  (3 * C2SZ)                // 26112
#define CTX2_SMEM (3 * C2STG)            // 78336

__global__ void __launch_bounds__(256, 2) k_context_tc(const __half* __restrict__ sh,
                                                       const __half* __restrict__ sl,
                                                       const __half* __restrict__ vh,
                                                       float* __restrict__ ctxp) {
    extern __shared__ char smem[];
    const uint32_t sb0 = smem_u32(smem);
    int tid = threadIdx.x, w = tid >> 5, lane = tid & 31;
    int head = blockIdx.x, bi = blockIdx.y, chunk = blockIdx.z;
    int bh = bi * HEADS + head;

    size_t base = ((size_t)bi * CH + head * DH) * NPIX + chunk * CK_N;
    const __half* s_h = sh + base;
    const __half* s_l = sl + base;
    const __half* v_h = vh + base;

    auto loadT = [&](int s, int p) {
        int n0 = p * 128;
        uint32_t sb = sb0 + (uint32_t)s * C2STG;
        #pragma unroll
        for (int i = 0; i < 2; i++) {
            int ch = tid + i * 256;
            int r = ch >> 4, c = ch & 15;
            size_t go = (size_t)r * NPIX + n0 + c * 8;
            uint32_t d = sb + r * C2P + c * 16;
            cp16(d, s_h + go);
            cp16(d + C2SZ, s_l + go);
            cp16(d + 2 * C2SZ, v_h + go);
        }
        asm volatile("cp.async.commit_group;" ::: "memory");
    };

    float acc[2][4][4];
    #pragma unroll
    for (int i = 0; i < 2; i++)
        #pragma unroll
        for (int j = 0; j < 4; j++)
            #pragma unroll
            for (int r = 0; r < 4; r++) acc[i][j][r] = 0.f;

    loadT(0, 0);
    loadT(1, 1);

    uint32_t cb = (uint32_t)w * 32 + (uint32_t)(lane >> 4) * 16;

    #pragma unroll
    for (int p = 0; p < 8; p++) {
        asm volatile("cp.async.wait_group 1;" ::: "memory");
        __syncthreads();
        if (p < 6) loadT((p + 2) % 3, p + 2);
        else asm volatile("cp.async.commit_group;" ::: "memory");

        uint32_t sb = sb0 + (uint32_t)(p % 3) * C2STG;
        uint32_t shf[2][4], slf[2][4];
        #pragma unroll
        for (int mi = 0; mi < 2; mi++) {
            uint32_t sa = sb + (uint32_t)(mi * 16 + (lane & 15)) * C2P + cb;
            ldsm4(shf[mi], sa);
            ldsm4(slf[mi], sa + C2SZ);
        }
        #pragma unroll
        for (int ei = 0; ei < 2; ei++) {
            uint32_t vhf[4];
            uint32_t va = sb + 2 * C2SZ + (uint32_t)(ei * 16 + (lane & 15)) * C2P + cb;
            ldsm4(vhf, va);
            #pragma unroll
            for (int pick = 0; pick < 2; pick++) {
                int nt = ei * 2 + pick;
                #pragma unroll
                for (int mi = 0; mi < 2; mi++) {
                    mma_fp16_2(acc[mi][nt], shf[mi], vhf[pick], vhf[pick + 2]);
                    mma_fp16_2(acc[mi][nt], slf[mi], vhf[pick], vhf[pick + 2]);
                }
            }
        }
    }

    // reduce across 8 warps via smem (overlays stages)
    __syncthreads();
    float* stage = (float*)smem + w * 1056;    // 32 x 33 per warp
    #pragma unroll
    for (int mi = 0; mi < 2; mi++)
        #pragma unroll
        for (int nt = 0; nt < 4; nt++) {
            int r0 = mi * 16 + (lane >> 2);
            int c0 = nt * 8 + (lane & 3) * 2;
            stage[r0 * 33 + c0]           = acc[mi][nt][0];
            stage[r0 * 33 + c0 + 1]       = acc[mi][nt][1];
            stage[(r0 + 8) * 33 + c0]     = acc[mi][nt][2];
            stage[(r0 + 8) * 33 + c0 + 1] = acc[mi][nt][3];
        }
    __syncthreads();
    {
        float* basep = (float*)smem;
        int j0 = tid * 4;
        int d = j0 >> 5, e = j0 & 31;
        float4 s = make_float4(0.f, 0.f, 0.f, 0.f);
        #pragma unroll
        for (int ww = 0; ww < 8; ww++) {
            float* p2 = basep + ww * 1056 + d * 33 + e;
            s.x += p2[0]; s.y += p2[1]; s.z += p2[2]; s.w += p2[3];
        }
        *(float4*)(ctxp + ((size_t)chunk * 256 + bh) * 1024 + j0) = s;
    }
}

// ---------------------------------------------------------------------------
// fused weight: ctx = (sum_c P_c) / z, Wf = w_out(head slice) @ ctx^T -> fp16 hi/lo
// ---------------------------------------------------------------------------
__global__ void __launch_bounds__(256) k_wf(const float* __restrict__ w_out,
                                            const float* __restrict__ ctxp,
                                            const float* __restrict__ zp,
                                            __half* __restrict__ wfh,
                                            __half* __restrict__ wfl) {
    int head = blockIdx.x, bi = blockIdx.y;
    int bh = bi * HEADS + head;
    __shared__ float cs[DH][33];
    __shared__ float z_s[DH];
    int tid = threadIdx.x;

    if (tid < 32) {
        const float* zrow = zp + ((size_t)bi * 256 + head * DH + tid) * 32;
        float zz = 0.f;
        #pragma unroll
        for (int c = 0; c < 32; c++) zz += zrow[c];
        z_s[tid] = zz;
    }
    __syncthreads();
    for (int i = tid; i < DH * DH; i += 256) {
        float s = 0.f;
        #pragma unroll
        for (int c = 0; c < CHUNKS; c++) s += ctxp[((size_t)c * 256 + bh) * 1024 + i];
        cs[i >> 5][i & 31] = s / z_s[i >> 5];
    }
    __syncthreads();

    int d = tid & 31, og = tid >> 5;
    for (int o = og; o < CH; o += 8) {
        const float* wrow = w_out + (size_t)o * CH + head * DH;
        float acc = 0.f;
        #pragma unroll
        for (int e = 0; e < DH; e++) acc += wrow[e] * cs[d][e];
        size_t oidx = (size_t)bi * CH * CH + (size_t)o * CH + head * DH + d;
        __half h = __float2half(acc);
        wfh[oidx] = h;
        wfl[oidx] = __float2half(acc - __half2float(h));
    }
}

// ---------------------------------------------------------------------------
extern "C" void kernel_launch(void* const* d_in, const int* in_sizes, int n_in,
                              void* d_out, int out_size) {
    const float* x     = (const float*)d_in[0];
    const float* w_qkv = (const float*)d_in[1];
    const float* w_out = (const float*)d_in[2];
    const float* b_out = (const float*)d_in[3];
    float* out = (float*)d_out;

    __half *xh, *wh, *qh, *sh, *sl, *vh, *wfh, *wfl;
    float *ctxp, *zp;
    cudaGetSymbolAddress((void**)&xh,   g_xh);
    cudaGetSymbolAddress((void**)&wh,   g_wh);
    cudaGetSymbolAddress((void**)&qh,   g_qh);
    cudaGetSymbolAddress((void**)&sh,   g_sh);
    cudaGetSymbolAddress((void**)&sl,   g_sl);
    cudaGetSymbolAddress((void**)&vh,   g_vh);
    cudaGetSymbolAddress((void**)&ctxp, g_ctxp);
    cudaGetSymbolAddress((void**)&zp,   g_zp);
    cudaGetSymbolAddress((void**)&wfh,  g_wfh);
    cudaGetSymbolAddress((void**)&wfl,  g_wfl);

    cudaFuncSetAttribute(k_sgemm<false>, cudaFuncAttributeMaxDynamicSharedMemorySize, SGEMM_SMEM_QKV);
    cudaFuncSetAttribute(k_sgemm<true>,  cudaFuncAttributeMaxDynamicSharedMemorySize, SGEMM_SMEM_OUT);
    cudaFuncSetAttribute(k_context_tc,   cudaFuncAttributeMaxDynamicSharedMemorySize, CTX2_SMEM);

    // 0. splits (both single fp16)
    k_split1<<<(BATCH * CH * FRAMES * NPIX) / 1024, 256>>>(x, xh);
    k_split1<<<(QKV_M * CH) / 1024, 256>>>(w_qkv, wh);
    // 1. QKV GEMM (1-product); epilogues: q softmax, k exp hi/lo + z, v single
    k_sgemm<false><<<dim3(NPIX / 128, QKV_M / 128, BF), 256, SGEMM_SMEM_QKV>>>(
        wh, nullptr, xh, nullptr, nullptr, qh, sh, sl, vh, zp);
    // 2. tensor-core context partials (2-product)
    k_context_tc<<<dim3(HEADS, BF, CHUNKS), 256, CTX2_SMEM>>>(sh, sl, vh, ctxp);
    // 3. fused weight -> fp16 hi/lo
    k_wf<<<dim3(HEADS, BF), 256>>>(w_out, ctxp, zp, wfh, wfl);
    // 4. output GEMM (2-product) + bias + scatter
    k_sgemm<true><<<dim3(NPIX / 128, CH / 128, BF), 256, SGEMM_SMEM_OUT>>>(
        wfh, wfl, qh, b_out, out, nullptr, nullptr, nullptr, nullptr, nullptr);
}